// round 1
// baseline (speedup 1.0000x reference)
#include <cuda_runtime.h>
#include <math.h>

// ---------------------------------------------------------------------------
// AttSRU: T=512, B=32, S=512, D=512, fp32.
// Round 1: correct multi-kernel implementation with register-tiled fp32 GEMMs.
// ---------------------------------------------------------------------------

namespace {
constexpr int  kT = 512, kB = 32, kS = 512, kD = 512;
constexpr long kTB   = (long)kT * kB;      // 16384 rows
constexpr long kTBD  = kTB * kD;           // 8388608
constexpr long kPRE  = kTB * 3 * kD;       // 25165824
constexpr float kEPS = 1e-6f;

// scratch layout (single __device__ array)
constexpr long OF_PRE  = 0;                 // [TB, 3D] raw preact
constexpr long OF_Z    = kPRE;              // [T,B,D] sigmoid(z)
constexpr long OF_HG   = OF_Z    + kTBD;    // [T,B,D] sigmoid(h_gate)
constexpr long OF_PL   = OF_HG   + kTBD;    // [T,B,D] pl_t (post-LN)
constexpr long OF_PCTX = OF_PL   + kTBD;    // [B,S,D] LN(enc@W_enc)
constexpr long OF_SS   = OF_PCTX + kTBD;    // [T,B,D] scan states
constexpr long OF_ATT  = OF_SS   + kTBD;    // [T,B,D] LN(ss@W_attn)
constexpr long OF_AV   = OF_ATT  + kTBD;    // [B,T,S] align -> softmax
constexpr long OF_AO   = OF_AV   + kTBD;    // [T,B,D] attn_out
constexpr long OF_H1   = OF_AO   + kTBD;    // [TB,D] ss@W_hidden
constexpr long OF_H2   = OF_H1   + kTBD;    // [TB,D] attn_out@W_ctx
constexpr long kSCRATCH = OF_H2  + kTBD;
}

__device__ float g_scratch[kSCRATCH];

// ---------------------------------------------------------------------------
// Reductions
// ---------------------------------------------------------------------------
__device__ __forceinline__ float warpSum(float v) {
#pragma unroll
    for (int o = 16; o; o >>= 1) v += __shfl_xor_sync(0xffffffffu, v, o);
    return v;
}
__device__ __forceinline__ float warpMax(float v) {
#pragma unroll
    for (int o = 16; o; o >>= 1) v = fmaxf(v, __shfl_xor_sync(0xffffffffu, v, o));
    return v;
}
__device__ __forceinline__ float blockSum(float v, float* sh) {
    int w = threadIdx.x >> 5, l = threadIdx.x & 31, nw = blockDim.x >> 5;
    v = warpSum(v);
    if (l == 0) sh[w] = v;
    __syncthreads();
    v = (l < nw) ? sh[l] : 0.f;
    v = warpSum(v);
    __syncthreads();
    return v;
}
__device__ __forceinline__ float blockMax(float v, float* sh) {
    int w = threadIdx.x >> 5, l = threadIdx.x & 31, nw = blockDim.x >> 5;
    v = warpMax(v);
    if (l == 0) sh[w] = v;
    __syncthreads();
    v = (l < nw) ? sh[l] : -INFINITY;
    v = warpMax(v);
    __syncthreads();
    return v;
}
__device__ __forceinline__ float sigm(float x) { return 1.f / (1.f + expf(-x)); }

// ---------------------------------------------------------------------------
// Register-tiled fp32 GEMM: C[M,N] = alpha * A[M,K] @ op(B)
//   BTRANS=false: op(B) = B, B stored [K x N] row-major (ldb = N-stride)
//   BTRANS=true : op(B) = B^T, B stored [N x K] row-major (ldb = K-stride)
// Requirements: M%128==0, N%128==0, K%8==0, 16B-aligned base pointers.
// Batched via blockIdx.z with strides sA/sB/sC.
// ---------------------------------------------------------------------------
template <bool BTRANS>
__global__ __launch_bounds__(256)
void gemm_kernel(const float* __restrict__ A, const float* __restrict__ B,
                 float* __restrict__ C, int K,
                 long lda, long ldb, long ldc,
                 long sA, long sB, long sC, float alpha)
{
    __shared__ float As[8][128];
    __shared__ float Bs[8][128];
    A += (long)blockIdx.z * sA;
    B += (long)blockIdx.z * sB;
    C += (long)blockIdx.z * sC;
    const int bm = blockIdx.y * 128;
    const int bn = blockIdx.x * 128;
    const int tid  = threadIdx.x;
    const int arow = tid >> 1, acol = (tid & 1) * 4;
    const int brow = tid >> 5, bcol = (tid & 31) * 4;
    const int ty = tid >> 4, tx = tid & 15;

    float acc[8][8] = {};
    for (int k0 = 0; k0 < K; k0 += 8) {
        float4 a4 = *reinterpret_cast<const float4*>(A + (long)(bm + arow) * lda + k0 + acol);
        As[acol + 0][arow] = a4.x; As[acol + 1][arow] = a4.y;
        As[acol + 2][arow] = a4.z; As[acol + 3][arow] = a4.w;
        if (BTRANS) {
            float4 b4 = *reinterpret_cast<const float4*>(B + (long)(bn + arow) * ldb + k0 + acol);
            Bs[acol + 0][arow] = b4.x; Bs[acol + 1][arow] = b4.y;
            Bs[acol + 2][arow] = b4.z; Bs[acol + 3][arow] = b4.w;
        } else {
            float4 b4 = *reinterpret_cast<const float4*>(B + (long)(k0 + brow) * ldb + bn + bcol);
            *reinterpret_cast<float4*>(&Bs[brow][bcol]) = b4;
        }
        __syncthreads();
#pragma unroll
        for (int kk = 0; kk < 8; kk++) {
            float ar[8], br[8];
#pragma unroll
            for (int i = 0; i < 8; i++) ar[i] = As[kk][ty * 8 + i];
#pragma unroll
            for (int j = 0; j < 8; j++) br[j] = Bs[kk][tx * 8 + j];
#pragma unroll
            for (int i = 0; i < 8; i++)
#pragma unroll
                for (int j = 0; j < 8; j++)
                    acc[i][j] = fmaf(ar[i], br[j], acc[i][j]);
        }
        __syncthreads();
    }
#pragma unroll
    for (int i = 0; i < 8; i++) {
        long row = bm + ty * 8 + i;
#pragma unroll
        for (int j = 0; j < 8; j += 4) {
            float4 o = make_float4(acc[i][j] * alpha, acc[i][j + 1] * alpha,
                                   acc[i][j + 2] * alpha, acc[i][j + 3] * alpha);
            *reinterpret_cast<float4*>(C + row * ldc + bn + tx * 8 + j) = o;
        }
    }
}

// ---------------------------------------------------------------------------
// LN over width 3D=1536, then split + sigmoid into Z / HG / PL buffers.
// blockDim = 384 (each thread one float4), grid = TB rows.
// ---------------------------------------------------------------------------
__global__ void ln_preact_kernel(const float* __restrict__ pre,
                                 const float* __restrict__ g, const float* __restrict__ bb,
                                 float* __restrict__ Z, float* __restrict__ HG,
                                 float* __restrict__ PL)
{
    __shared__ float sh[32];
    long row = blockIdx.x;
    int c = threadIdx.x * 4;
    const float* r = pre + row * (3 * kD);
    float4 v = *reinterpret_cast<const float4*>(r + c);
    float s = v.x + v.y + v.z + v.w;
    float q = v.x * v.x + v.y * v.y + v.z * v.z + v.w * v.w;
    s = blockSum(s, sh);
    q = blockSum(q, sh);
    const float invW = 1.f / (3 * kD);
    float m  = s * invW;
    float rv = rsqrtf(q * invW - m * m + kEPS);
    float n0 = g[c + 0] * ((v.x - m) * rv) + bb[c + 0];
    float n1 = g[c + 1] * ((v.y - m) * rv) + bb[c + 1];
    float n2 = g[c + 2] * ((v.z - m) * rv) + bb[c + 2];
    float n3 = g[c + 3] * ((v.w - m) * rv) + bb[c + 3];
    long rD = row * kD;
    if (c < kD) {
        float4 o = make_float4(sigm(n0), sigm(n1), sigm(n2), sigm(n3));
        *reinterpret_cast<float4*>(Z + rD + c) = o;
    } else if (c < 2 * kD) {
        float4 o = make_float4(sigm(n0), sigm(n1), sigm(n2), sigm(n3));
        *reinterpret_cast<float4*>(HG + rD + (c - kD)) = o;
    } else {
        float4 o = make_float4(n0, n1, n2, n3);
        *reinterpret_cast<float4*>(PL + rD + (c - 2 * kD)) = o;
    }
}

// In-place LN over width D=512. blockDim = 128, grid = rows.
__global__ void ln512_kernel(float* __restrict__ x,
                             const float* __restrict__ g, const float* __restrict__ b)
{
    __shared__ float sh[32];
    long row = blockIdx.x;
    int c = threadIdx.x * 4;
    float* r = x + row * kD;
    float4 v = *reinterpret_cast<const float4*>(r + c);
    float s = v.x + v.y + v.z + v.w;
    float q = v.x * v.x + v.y * v.y + v.z * v.z + v.w * v.w;
    s = blockSum(s, sh);
    q = blockSum(q, sh);
    const float invW = 1.f / kD;
    float m  = s * invW;
    float rv = rsqrtf(q * invW - m * m + kEPS);
    v.x = g[c + 0] * ((v.x - m) * rv) + b[c + 0];
    v.y = g[c + 1] * ((v.y - m) * rv) + b[c + 1];
    v.z = g[c + 2] * ((v.z - m) * rv) + b[c + 2];
    v.w = g[c + 3] * ((v.w - m) * rv) + b[c + 3];
    *reinterpret_cast<float4*>(r + c) = v;
}

// SRU linear recurrence: one thread per (b,d) lane, sequential over T.
__global__ void scan_kernel(const float* __restrict__ Z, const float* __restrict__ PL,
                            const float* __restrict__ h0, float* __restrict__ ss)
{
    int idx = blockIdx.x * blockDim.x + threadIdx.x;   // b*D + d
    float s = h0[idx];
    long off = idx;
    const long stride = (long)kB * kD;
    for (int t = 0; t < kT; t++) {
        float z = Z[off];
        float p = PL[off];
        s = (1.f - z) * s + z * p;
        ss[off] = s;
        off += stride;
    }
}

// Masked softmax over S=512 with 1/sqrt(D) scaling; in-place into av ([B,T,S])
// and transposed copy into p_attn output ([T,B,S]).
__global__ void softmax_kernel(float* __restrict__ av, float* __restrict__ pattn,
                               const int* __restrict__ mlen)
{
    __shared__ float sh[32];
    long row = blockIdx.x;                 // b*T + t
    int b = (int)(row / kT), t = (int)(row % kT);
    int ml = mlen[b];
    float* r = av + row * kS;
    int c = threadIdx.x * 4;
    float4 v = *reinterpret_cast<const float4*>(r + c);
    const float inv = rsqrtf((float)kD);
    float x0 = v.x * inv, x1 = v.y * inv, x2 = v.z * inv, x3 = v.w * inv;
    float mx = -INFINITY;
    if (c + 0 < ml) mx = fmaxf(mx, x0);
    if (c + 1 < ml) mx = fmaxf(mx, x1);
    if (c + 2 < ml) mx = fmaxf(mx, x2);
    if (c + 3 < ml) mx = fmaxf(mx, x3);
    mx = blockMax(mx, sh);
    float e0 = (c + 0 < ml) ? expf(x0 - mx) : 0.f;
    float e1 = (c + 1 < ml) ? expf(x1 - mx) : 0.f;
    float e2 = (c + 2 < ml) ? expf(x2 - mx) : 0.f;
    float e3 = (c + 3 < ml) ? expf(x3 - mx) : 0.f;
    float sum = blockSum(e0 + e1 + e2 + e3, sh);
    float is = 1.f / sum;
    float4 o = make_float4(e0 * is, e1 * is, e2 * is, e3 * is);
    *reinterpret_cast<float4*>(r + c) = o;
    *reinterpret_cast<float4*>(pattn + ((long)t * kB + b) * kS + c) = o;
}

// Final: out = (1-hg)*tanh(LN(h1;g_h,b_h) + LN(h2;g_c,b_c)) + hg*prev
__global__ void final_kernel(const float* __restrict__ h1, const float* __restrict__ h2,
                             const float* __restrict__ HG, const float* __restrict__ prev,
                             const float* __restrict__ g_h, const float* __restrict__ b_h,
                             const float* __restrict__ g_c, const float* __restrict__ b_c,
                             float* __restrict__ out)
{
    __shared__ float sh[32];
    long row = blockIdx.x;
    int c = threadIdx.x * 4;
    float4 a = *reinterpret_cast<const float4*>(h1 + row * kD + c);
    float4 d = *reinterpret_cast<const float4*>(h2 + row * kD + c);
    float s1 = a.x + a.y + a.z + a.w;
    float q1 = a.x * a.x + a.y * a.y + a.z * a.z + a.w * a.w;
    float s2 = d.x + d.y + d.z + d.w;
    float q2 = d.x * d.x + d.y * d.y + d.z * d.z + d.w * d.w;
    s1 = blockSum(s1, sh);
    q1 = blockSum(q1, sh);
    s2 = blockSum(s2, sh);
    q2 = blockSum(q2, sh);
    const float invW = 1.f / kD;
    float m1 = s1 * invW, r1 = rsqrtf(q1 * invW - m1 * m1 + kEPS);
    float m2 = s2 * invW, r2 = rsqrtf(q2 * invW - m2 * m2 + kEPS);
    float4 hg = *reinterpret_cast<const float4*>(HG + row * kD + c);
    float4 pv = *reinterpret_cast<const float4*>(prev + row * kD + c);
    float t0 = tanhf(g_h[c + 0] * ((a.x - m1) * r1) + b_h[c + 0] +
                     g_c[c + 0] * ((d.x - m2) * r2) + b_c[c + 0]);
    float t1 = tanhf(g_h[c + 1] * ((a.y - m1) * r1) + b_h[c + 1] +
                     g_c[c + 1] * ((d.y - m2) * r2) + b_c[c + 1]);
    float t2 = tanhf(g_h[c + 2] * ((a.z - m1) * r1) + b_h[c + 2] +
                     g_c[c + 2] * ((d.z - m2) * r2) + b_c[c + 2]);
    float t3 = tanhf(g_h[c + 3] * ((a.w - m1) * r1) + b_h[c + 3] +
                     g_c[c + 3] * ((d.w - m2) * r2) + b_c[c + 3]);
    float4 o;
    o.x = (1.f - hg.x) * t0 + hg.x * pv.x;
    o.y = (1.f - hg.y) * t1 + hg.y * pv.y;
    o.z = (1.f - hg.z) * t2 + hg.z * pv.z;
    o.w = (1.f - hg.w) * t3 + hg.w * pv.w;
    *reinterpret_cast<float4*>(out + row * kD + c) = o;
}

// ---------------------------------------------------------------------------
// Launch
// ---------------------------------------------------------------------------
extern "C" void kernel_launch(void* const* d_in, const int* in_sizes, int n_in,
                              void* d_out, int out_size)
{
    // Resolve inputs by element-count signature (robust to metadata ordering;
    // same-size groups keep their relative order in both candidate orderings).
    int i_prev = -1, i_enc = -1, i_hidden = -1, i_ml = -1, i_Win = -1;
    int w4[4] = {-1, -1, -1, -1}; int n4 = 0;
    int p2[2] = {-1, -1};         int np = 0;
    int v8[8] = {-1, -1, -1, -1, -1, -1, -1, -1}; int nv = 0;
    for (int i = 0; i < n_in; i++) {
        switch (in_sizes[i]) {
            case 8388608: if (i_prev < 0) i_prev = i; else i_enc = i; break;
            case 16384:   i_hidden = i; break;
            case 32:      i_ml = i; break;
            case 786432:  i_Win = i; break;
            case 262144:  if (n4 < 4) w4[n4++] = i; break;
            case 1536:    if (np < 2) p2[np++] = i; break;
            case 512:     if (nv < 8) v8[nv++] = i; break;
            default: break;
        }
    }
    const float* prev   = (const float*)d_in[i_prev];
    const float* hidden = (const float*)d_in[i_hidden];
    const float* enc    = (const float*)d_in[i_enc];
    const int*   mlen   = (const int*)d_in[i_ml];
    const float* W_in   = (const float*)d_in[i_Win];
    const float* W_enc  = (const float*)d_in[w4[0]];
    const float* W_att  = (const float*)d_in[w4[1]];
    const float* W_hid  = (const float*)d_in[w4[2]];
    const float* W_ctx  = (const float*)d_in[w4[3]];
    const float* g_pre  = (const float*)d_in[p2[0]];
    const float* b_pre  = (const float*)d_in[p2[1]];
    const float* g_enc  = (const float*)d_in[v8[0]];
    const float* b_enc  = (const float*)d_in[v8[1]];
    const float* g_att  = (const float*)d_in[v8[2]];
    const float* b_att  = (const float*)d_in[v8[3]];
    const float* g_h    = (const float*)d_in[v8[4]];
    const float* b_h    = (const float*)d_in[v8[5]];
    const float* g_c    = (const float*)d_in[v8[6]];
    const float* b_c    = (const float*)d_in[v8[7]];

    float* sc = nullptr;
    cudaGetSymbolAddress((void**)&sc, g_scratch);

    float* out       = (float*)d_out;            // [T,B,D]
    float* out_hid   = out + kTBD;               // [B,D]
    float* out_pattn = out_hid + (long)kB * kD;  // [T,B,S]

    dim3 blk(256);

    // 1) preact_raw = prev @ W_in                      [16384 x 1536]
    gemm_kernel<false><<<dim3(12, 128, 1), blk>>>(prev, W_in, sc + OF_PRE, 512,
                                                  512, 1536, 1536, 0, 0, 0, 1.f);
    // 2) LN(3D) + split + sigmoid -> Z, HG, PL
    ln_preact_kernel<<<(unsigned)kTB, 384>>>(sc + OF_PRE, g_pre, b_pre,
                                             sc + OF_Z, sc + OF_HG, sc + OF_PL);
    // 3) pctx = LN(enc @ W_enc)                        [16384 x 512]
    gemm_kernel<false><<<dim3(4, 128, 1), blk>>>(enc, W_enc, sc + OF_PCTX, 512,
                                                 512, 512, 512, 0, 0, 0, 1.f);
    ln512_kernel<<<(unsigned)kTB, 128>>>(sc + OF_PCTX, g_enc, b_enc);
    // 4) SRU scan -> ss
    scan_kernel<<<(kB * kD) / 256, 256>>>(sc + OF_Z, sc + OF_PL, hidden, sc + OF_SS);
    // 5) attn_in = LN(ss @ W_attn)
    gemm_kernel<false><<<dim3(4, 128, 1), blk>>>(sc + OF_SS, W_att, sc + OF_ATT, 512,
                                                 512, 512, 512, 0, 0, 0, 1.f);
    ln512_kernel<<<(unsigned)kTB, 128>>>(sc + OF_ATT, g_att, b_att);
    // 6) align[b] = attn_in_b [T,D] @ pctx_b^T [S,D]   (batched NT)
    gemm_kernel<true><<<dim3(4, 4, 32), blk>>>(sc + OF_ATT, sc + OF_PCTX, sc + OF_AV, 512,
                                               (long)kB * kD, 512, 512,
                                               kD, (long)kS * kD, (long)kT * kS, 1.f);
    // 7) masked softmax (also writes p_attn output)
    softmax_kernel<<<(unsigned)(kB * kT), 128>>>(sc + OF_AV, out_pattn, mlen);
    // 8) attn_out = (av @ pctx) / sqrt(D)              (batched NN, alpha)
    gemm_kernel<false><<<dim3(4, 4, 32), blk>>>(sc + OF_AV, sc + OF_PCTX, sc + OF_AO, 512,
                                                512, 512, (long)kB * kD,
                                                (long)kT * kS, (long)kS * kD, kD,
                                                rsqrtf((float)kD));
    // 9) h1 = ss @ W_hidden ; h2 = attn_out @ W_ctx
    gemm_kernel<false><<<dim3(4, 128, 1), blk>>>(sc + OF_SS, W_hid, sc + OF_H1, 512,
                                                 512, 512, 512, 0, 0, 0, 1.f);
    gemm_kernel<false><<<dim3(4, 128, 1), blk>>>(sc + OF_AO, W_ctx, sc + OF_H2, 512,
                                                 512, 512, 512, 0, 0, 0, 1.f);
    // 10) out = (1-hg)*tanh(LN(h1)+LN(h2)) + hg*prev
    final_kernel<<<(unsigned)kTB, 128>>>(sc + OF_H1, sc + OF_H2, sc + OF_HG, prev,
                                         g_h, b_h, g_c, b_c, out);
    // 11) hidden_last = ss[T-1]
    cudaMemcpyAsync(out_hid, sc + OF_SS + (long)(kT - 1) * kB * kD,
                    (size_t)kB * kD * sizeof(float), cudaMemcpyDeviceToDevice, 0);
}

// round 3
// speedup vs baseline: 2.9033x; 2.9033x over previous
#include <cuda_runtime.h>
#include <math.h>
#include <stdint.h>

// ---------------------------------------------------------------------------
// AttSRU: T=512, B=32, S=512, D=512, fp32.
// Round 3: GEMMs via mma.sync.m16n8k8 tf32 (sm_80+ PTX; harness targets plain
// sm_103, so tcgen05 is unavailable). cp.async 2-stage pipeline, 128x128x32.
// ---------------------------------------------------------------------------

namespace {
constexpr int  kT = 512, kB = 32, kS = 512, kD = 512;
constexpr long kTB   = (long)kT * kB;      // 16384 rows
constexpr long kTBD  = kTB * kD;           // 8388608
constexpr long kPRE  = kTB * 3 * kD;       // 25165824
constexpr float kEPS = 1e-6f;

// scratch layout (single __device__ array)
constexpr long OF_PRE   = 0;                 // [TB, 3D] raw preact
constexpr long OF_Z     = kPRE;              // [T,B,D] sigmoid(z)
constexpr long OF_HG    = OF_Z    + kTBD;    // [T,B,D] sigmoid(h_gate)
constexpr long OF_PL    = OF_HG   + kTBD;    // [T,B,D] pl_t
constexpr long OF_PCTX  = OF_PL   + kTBD;    // [B,S,D] LN(enc@W_enc)
constexpr long OF_SS    = OF_PCTX + kTBD;    // [T,B,D] scan states
constexpr long OF_ATT   = OF_SS   + kTBD;    // [T,B,D] LN(ss@W_attn)
constexpr long OF_AV    = OF_ATT  + kTBD;    // [B,T,S] align -> softmax
constexpr long OF_AO    = OF_AV   + kTBD;    // [T,B,D] attn_out
constexpr long OF_H1    = OF_AO   + kTBD;    // [TB,D]
constexpr long OF_H2    = OF_H1   + kTBD;    // [TB,D]
constexpr long OF_PCTXT = OF_H2   + kTBD;    // [B,D,S] pctx transposed
constexpr long OF_WTIN  = OF_PCTXT + kTBD;   // [3D,D]
constexpr long OF_WTENC = OF_WTIN  + (long)3 * kD * kD;
constexpr long OF_WTATT = OF_WTENC + (long)kD * kD;
constexpr long OF_WTHID = OF_WTATT + (long)kD * kD;
constexpr long OF_WTCTX = OF_WTHID + (long)kD * kD;
constexpr long kSCRATCH = OF_WTCTX + (long)kD * kD;

// GEMM smem: row stride 36 floats (conflict-free frag reads, 16B aligned)
constexpr int RS = 36;                        // floats per smem row
constexpr int OP_FLOATS = 128 * RS;           // one operand per stage
constexpr int STAGE_FLOATS = 2 * OP_FLOATS;   // A + B
constexpr int GEMM_SMEM = 2 * STAGE_FLOATS * 4;   // 2 stages -> 73728 B
}

__device__ float g_scratch[kSCRATCH];

// ---------------------------------------------------------------------------
// Helpers
// ---------------------------------------------------------------------------
__device__ __forceinline__ float warpSum(float v) {
#pragma unroll
    for (int o = 16; o; o >>= 1) v += __shfl_xor_sync(0xffffffffu, v, o);
    return v;
}
__device__ __forceinline__ float warpMax(float v) {
#pragma unroll
    for (int o = 16; o; o >>= 1) v = fmaxf(v, __shfl_xor_sync(0xffffffffu, v, o));
    return v;
}
__device__ __forceinline__ float blockSum(float v, float* sh) {
    int w = threadIdx.x >> 5, l = threadIdx.x & 31, nw = blockDim.x >> 5;
    v = warpSum(v);
    if (l == 0) sh[w] = v;
    __syncthreads();
    v = (l < nw) ? sh[l] : 0.f;
    v = warpSum(v);
    __syncthreads();
    return v;
}
__device__ __forceinline__ float blockMax(float v, float* sh) {
    int w = threadIdx.x >> 5, l = threadIdx.x & 31, nw = blockDim.x >> 5;
    v = warpMax(v);
    if (l == 0) sh[w] = v;
    __syncthreads();
    v = (l < nw) ? sh[l] : -INFINITY;
    v = warpMax(v);
    __syncthreads();
    return v;
}
__device__ __forceinline__ float sigm(float x) { return 1.f / (1.f + expf(-x)); }
// round-to-nearest tf32 (kills truncation bias in the tensor unit)
__device__ __forceinline__ float tf32r(float x) {
    uint32_t u;
    asm("cvt.rna.tf32.f32 %0, %1;" : "=r"(u) : "f"(x));
    return __uint_as_float(u);
}

// ---------------------------------------------------------------------------
// tf32 mma.sync GEMM: C[M,N] = alpha * A[M,K] @ B[N,K]^T   (NT form)
// A, B fp32 row-major K-major (lda/ldb = element row strides).
// M%128==0, N%128==0, K%32==0. Batched via blockIdx.z strides.
// Grid: (N/128, M/128, batch). Block: 256 (8 warps, 4x2, warp tile 32x64).
// ---------------------------------------------------------------------------
__global__ __launch_bounds__(256, 2)
void gemm_mma_kernel(const float* __restrict__ A, const float* __restrict__ B,
                     float* __restrict__ C, int K,
                     long lda, long ldb, long ldc,
                     long sA, long sB, long sC, float alpha)
{
    extern __shared__ float smem[];
    A += (long)blockIdx.z * sA;
    B += (long)blockIdx.z * sB;
    C += (long)blockIdx.z * sC;
    const int bm = blockIdx.y * 128, bn = blockIdx.x * 128;
    const int tid = threadIdx.x, wid = tid >> 5, lane = tid & 31;
    const int mw = (wid >> 1) * 32;        // warp m offset in tile
    const int nw = (wid & 1) * 64;         // warp n offset in tile
    const int lr = lane >> 2;              // 0..7
    const int lc = lane & 3;               // 0..3

    // cp.async slot mapping: 4 float4 per thread per operand
    int rowi[4], qi[4];
#pragma unroll
    for (int t = 0; t < 4; t++) {
        int id = tid + t * 256;            // 0..1023
        rowi[t] = id >> 3;
        qi[t]   = id & 7;
    }
    const int nch = K >> 5;                // K/32 chunks

    auto load_chunk = [&](int c, int s) {
        float* As = smem + s * STAGE_FLOATS;
        float* Bs = As + OP_FLOATS;
        long ko = (long)c * 32;
#pragma unroll
        for (int t = 0; t < 4; t++) {
            const float* ga = A + (long)(bm + rowi[t]) * lda + ko + qi[t] * 4;
            float* da = As + rowi[t] * RS + qi[t] * 4;
            asm volatile("cp.async.cg.shared.global [%0], [%1], 16;"
                         :: "r"((uint32_t)__cvta_generic_to_shared(da)), "l"(ga));
        }
#pragma unroll
        for (int t = 0; t < 4; t++) {
            const float* gb = B + (long)(bn + rowi[t]) * ldb + ko + qi[t] * 4;
            float* db = Bs + rowi[t] * RS + qi[t] * 4;
            asm volatile("cp.async.cg.shared.global [%0], [%1], 16;"
                         :: "r"((uint32_t)__cvta_generic_to_shared(db)), "l"(gb));
        }
    };

    float acc[2][8][4];
#pragma unroll
    for (int i = 0; i < 2; i++)
#pragma unroll
        for (int j = 0; j < 8; j++)
#pragma unroll
            for (int v = 0; v < 4; v++) acc[i][j][v] = 0.f;

    load_chunk(0, 0);
    asm volatile("cp.async.commit_group;");
    if (nch > 1) {
        load_chunk(1, 1);
        asm volatile("cp.async.commit_group;");
    }

    for (int c = 0; c < nch; c++) {
        if (c + 2 <= nch) asm volatile("cp.async.wait_group 1;");
        else              asm volatile("cp.async.wait_group 0;");
        __syncthreads();
        const float* As = smem + (c & 1) * STAGE_FLOATS;
        const float* Bs = As + OP_FLOATS;
#pragma unroll
        for (int kk = 0; kk < 4; kk++) {
            const int k0 = kk * 8;
            uint32_t a[2][4];
#pragma unroll
            for (int im = 0; im < 2; im++) {
                const float* ap = As + (mw + im * 16 + lr) * RS + k0 + lc;
                a[im][0] = __float_as_uint(ap[0]);
                a[im][1] = __float_as_uint(ap[8 * RS]);
                a[im][2] = __float_as_uint(ap[4]);
                a[im][3] = __float_as_uint(ap[8 * RS + 4]);
            }
#pragma unroll
            for (int jn = 0; jn < 8; jn++) {
                const float* bp = Bs + (nw + jn * 8 + lr) * RS + k0 + lc;
                uint32_t b0 = __float_as_uint(bp[0]);
                uint32_t b1 = __float_as_uint(bp[4]);
#pragma unroll
                for (int im = 0; im < 2; im++) {
                    asm volatile(
                        "mma.sync.aligned.m16n8k8.row.col.f32.tf32.tf32.f32 "
                        "{%0,%1,%2,%3}, {%4,%5,%6,%7}, {%8,%9}, {%0,%1,%2,%3};"
                        : "+f"(acc[im][jn][0]), "+f"(acc[im][jn][1]),
                          "+f"(acc[im][jn][2]), "+f"(acc[im][jn][3])
                        : "r"(a[im][0]), "r"(a[im][1]), "r"(a[im][2]), "r"(a[im][3]),
                          "r"(b0), "r"(b1));
                }
            }
        }
        __syncthreads();
        if (c + 2 < nch) {
            load_chunk(c + 2, c & 1);
            asm volatile("cp.async.commit_group;");
        }
    }

    // epilogue: direct float2 stores
#pragma unroll
    for (int im = 0; im < 2; im++) {
        long r0 = (long)(bm + mw + im * 16 + lr);
#pragma unroll
        for (int jn = 0; jn < 8; jn++) {
            long col = bn + nw + jn * 8 + lc * 2;
            float2 v0 = make_float2(acc[im][jn][0] * alpha, acc[im][jn][1] * alpha);
            float2 v1 = make_float2(acc[im][jn][2] * alpha, acc[im][jn][3] * alpha);
            *reinterpret_cast<float2*>(C + r0 * ldc + col) = v0;
            *reinterpret_cast<float2*>(C + (r0 + 8) * ldc + col) = v1;
        }
    }
}

// ---------------------------------------------------------------------------
// Transpose: in [R,C] -> out [C,R], output rounded to tf32 (RNA).
// blockDim (32,8), grid (C/32, R/32, batch).
// ---------------------------------------------------------------------------
__global__ void transpose_kernel(const float* __restrict__ in, float* __restrict__ out,
                                 int R, int C, long sIn, long sOut)
{
    __shared__ float t[32][33];
    in  += (long)blockIdx.z * sIn;
    out += (long)blockIdx.z * sOut;
    int bx = blockIdx.x * 32, by = blockIdx.y * 32;
    int x = threadIdx.x, y = threadIdx.y;
#pragma unroll
    for (int i = 0; i < 32; i += 8) t[y + i][x] = in[(long)(by + y + i) * C + bx + x];
    __syncthreads();
#pragma unroll
    for (int i = 0; i < 32; i += 8)
        out[(long)(bx + y + i) * R + by + x] = tf32r(t[x][y + i]);
}

// ---------------------------------------------------------------------------
// LN over 3D=1536, split + sigmoid into Z / HG / PL. block=384, grid=TB.
// ---------------------------------------------------------------------------
__global__ void ln_preact_kernel(const float* __restrict__ pre,
                                 const float* __restrict__ g, const float* __restrict__ bb,
                                 float* __restrict__ Z, float* __restrict__ HG,
                                 float* __restrict__ PL)
{
    __shared__ float sh[32];
    long row = blockIdx.x;
    int c = threadIdx.x * 4;
    const float* r = pre + row * (3 * kD);
    float4 v = *reinterpret_cast<const float4*>(r + c);
    float s = v.x + v.y + v.z + v.w;
    float q = v.x * v.x + v.y * v.y + v.z * v.z + v.w * v.w;
    s = blockSum(s, sh);
    q = blockSum(q, sh);
    const float invW = 1.f / (3 * kD);
    float m  = s * invW;
    float rv = rsqrtf(q * invW - m * m + kEPS);
    float n0 = g[c + 0] * ((v.x - m) * rv) + bb[c + 0];
    float n1 = g[c + 1] * ((v.y - m) * rv) + bb[c + 1];
    float n2 = g[c + 2] * ((v.z - m) * rv) + bb[c + 2];
    float n3 = g[c + 3] * ((v.w - m) * rv) + bb[c + 3];
    long rD = row * kD;
    if (c < kD) {
        float4 o = make_float4(sigm(n0), sigm(n1), sigm(n2), sigm(n3));
        *reinterpret_cast<float4*>(Z + rD + c) = o;
    } else if (c < 2 * kD) {
        float4 o = make_float4(sigm(n0), sigm(n1), sigm(n2), sigm(n3));
        *reinterpret_cast<float4*>(HG + rD + (c - kD)) = o;
    } else {
        float4 o = make_float4(n0, n1, n2, n3);
        *reinterpret_cast<float4*>(PL + rD + (c - 2 * kD)) = o;
    }
}

// In-place LN over D=512, output rounded to tf32. block=128, grid=rows.
__global__ void ln512_kernel(float* __restrict__ x,
                             const float* __restrict__ g, const float* __restrict__ b)
{
    __shared__ float sh[32];
    long row = blockIdx.x;
    int c = threadIdx.x * 4;
    float* r = x + row * kD;
    float4 v = *reinterpret_cast<const float4*>(r + c);
    float s = v.x + v.y + v.z + v.w;
    float q = v.x * v.x + v.y * v.y + v.z * v.z + v.w * v.w;
    s = blockSum(s, sh);
    q = blockSum(q, sh);
    const float invW = 1.f / kD;
    float m  = s * invW;
    float rv = rsqrtf(q * invW - m * m + kEPS);
    v.x = tf32r(g[c + 0] * ((v.x - m) * rv) + b[c + 0]);
    v.y = tf32r(g[c + 1] * ((v.y - m) * rv) + b[c + 1]);
    v.z = tf32r(g[c + 2] * ((v.z - m) * rv) + b[c + 2]);
    v.w = tf32r(g[c + 3] * ((v.w - m) * rv) + b[c + 3]);
    *reinterpret_cast<float4*>(r + c) = v;
}

// SRU linear recurrence
__global__ void scan_kernel(const float* __restrict__ Z, const float* __restrict__ PL,
                            const float* __restrict__ h0, float* __restrict__ ss)
{
    int idx = blockIdx.x * blockDim.x + threadIdx.x;   // b*D + d
    float s = h0[idx];
    long off = idx;
    const long stride = (long)kB * kD;
    for (int t = 0; t < kT; t++) {
        float z = Z[off];
        float p = PL[off];
        s = (1.f - z) * s + z * p;
        ss[off] = s;
        off += stride;
    }
}

// Masked softmax over S=512; rounded probs into av (GEMM operand),
// exact probs into p_attn output.
__global__ void softmax_kernel(float* __restrict__ av, float* __restrict__ pattn,
                               const int* __restrict__ mlen)
{
    __shared__ float sh[32];
    long row = blockIdx.x;                 // b*T + t
    int b = (int)(row / kT), t = (int)(row % kT);
    int ml = mlen[b];
    float* r = av + row * kS;
    int c = threadIdx.x * 4;
    float4 v = *reinterpret_cast<const float4*>(r + c);
    const float inv = rsqrtf((float)kD);
    float x0 = v.x * inv, x1 = v.y * inv, x2 = v.z * inv, x3 = v.w * inv;
    float mx = -INFINITY;
    if (c + 0 < ml) mx = fmaxf(mx, x0);
    if (c + 1 < ml) mx = fmaxf(mx, x1);
    if (c + 2 < ml) mx = fmaxf(mx, x2);
    if (c + 3 < ml) mx = fmaxf(mx, x3);
    mx = blockMax(mx, sh);
    float e0 = (c + 0 < ml) ? expf(x0 - mx) : 0.f;
    float e1 = (c + 1 < ml) ? expf(x1 - mx) : 0.f;
    float e2 = (c + 2 < ml) ? expf(x2 - mx) : 0.f;
    float e3 = (c + 3 < ml) ? expf(x3 - mx) : 0.f;
    float sum = blockSum(e0 + e1 + e2 + e3, sh);
    float is = 1.f / sum;
    float4 o = make_float4(e0 * is, e1 * is, e2 * is, e3 * is);
    *reinterpret_cast<float4*>(pattn + ((long)t * kB + b) * kS + c) = o;
    float4 oq = make_float4(tf32r(o.x), tf32r(o.y), tf32r(o.z), tf32r(o.w));
    *reinterpret_cast<float4*>(r + c) = oq;
}

// out = (1-hg)*tanh(LN(h1)+LN(h2)) + hg*prev
__global__ void final_kernel(const float* __restrict__ h1, const float* __restrict__ h2,
                             const float* __restrict__ HG, const float* __restrict__ prev,
                             const float* __restrict__ g_h, const float* __restrict__ b_h,
                             const float* __restrict__ g_c, const float* __restrict__ b_c,
                             float* __restrict__ out)
{
    __shared__ float sh[32];
    long row = blockIdx.x;
    int c = threadIdx.x * 4;
    float4 a = *reinterpret_cast<const float4*>(h1 + row * kD + c);
    float4 d = *reinterpret_cast<const float4*>(h2 + row * kD + c);
    float s1 = a.x + a.y + a.z + a.w;
    float q1 = a.x * a.x + a.y * a.y + a.z * a.z + a.w * a.w;
    float s2 = d.x + d.y + d.z + d.w;
    float q2 = d.x * d.x + d.y * d.y + d.z * d.z + d.w * d.w;
    s1 = blockSum(s1, sh);
    q1 = blockSum(q1, sh);
    s2 = blockSum(s2, sh);
    q2 = blockSum(q2, sh);
    const float invW = 1.f / kD;
    float m1 = s1 * invW, r1 = rsqrtf(q1 * invW - m1 * m1 + kEPS);
    float m2 = s2 * invW, r2 = rsqrtf(q2 * invW - m2 * m2 + kEPS);
    float4 hg = *reinterpret_cast<const float4*>(HG + row * kD + c);
    float4 pv = *reinterpret_cast<const float4*>(prev + row * kD + c);
    float t0 = tanhf(g_h[c + 0] * ((a.x - m1) * r1) + b_h[c + 0] +
                     g_c[c + 0] * ((d.x - m2) * r2) + b_c[c + 0]);
    float t1 = tanhf(g_h[c + 1] * ((a.y - m1) * r1) + b_h[c + 1] +
                     g_c[c + 1] * ((d.y - m2) * r2) + b_c[c + 1]);
    float t2 = tanhf(g_h[c + 2] * ((a.z - m1) * r1) + b_h[c + 2] +
                     g_c[c + 2] * ((d.z - m2) * r2) + b_c[c + 2]);
    float t3 = tanhf(g_h[c + 3] * ((a.w - m1) * r1) + b_h[c + 3] +
                     g_c[c + 3] * ((d.w - m2) * r2) + b_c[c + 3]);
    float4 o;
    o.x = (1.f - hg.x) * t0 + hg.x * pv.x;
    o.y = (1.f - hg.y) * t1 + hg.y * pv.y;
    o.z = (1.f - hg.z) * t2 + hg.z * pv.z;
    o.w = (1.f - hg.w) * t3 + hg.w * pv.w;
    *reinterpret_cast<float4*>(out + row * kD + c) = o;
}

// ---------------------------------------------------------------------------
// Launch
// ---------------------------------------------------------------------------
extern "C" void kernel_launch(void* const* d_in, const int* in_sizes, int n_in,
                              void* d_out, int out_size)
{
    int i_prev = -1, i_enc = -1, i_hidden = -1, i_ml = -1, i_Win = -1;
    int w4[4] = {-1, -1, -1, -1}; int n4 = 0;
    int p2[2] = {-1, -1};         int np = 0;
    int v8[8] = {-1, -1, -1, -1, -1, -1, -1, -1}; int nv = 0;
    for (int i = 0; i < n_in; i++) {
        switch (in_sizes[i]) {
            case 8388608: if (i_prev < 0) i_prev = i; else i_enc = i; break;
            case 16384:   i_hidden = i; break;
            case 32:      i_ml = i; break;
            case 786432:  i_Win = i; break;
            case 262144:  if (n4 < 4) w4[n4++] = i; break;
            case 1536:    if (np < 2) p2[np++] = i; break;
            case 512:     if (nv < 8) v8[nv++] = i; break;
            default: break;
        }
    }
    const float* prev   = (const float*)d_in[i_prev];
    const float* hidden = (const float*)d_in[i_hidden];
    const float* enc    = (const float*)d_in[i_enc];
    const int*   mlen   = (const int*)d_in[i_ml];
    const float* W_in   = (const float*)d_in[i_Win];
    const float* W_enc  = (const float*)d_in[w4[0]];
    const float* W_att  = (const float*)d_in[w4[1]];
    const float* W_hid  = (const float*)d_in[w4[2]];
    const float* W_ctx  = (const float*)d_in[w4[3]];
    const float* g_pre  = (const float*)d_in[p2[0]];
    const float* b_pre  = (const float*)d_in[p2[1]];
    const float* g_enc  = (const float*)d_in[v8[0]];
    const float* b_enc  = (const float*)d_in[v8[1]];
    const float* g_att  = (const float*)d_in[v8[2]];
    const float* b_att  = (const float*)d_in[v8[3]];
    const float* g_h    = (const float*)d_in[v8[4]];
    const float* b_h    = (const float*)d_in[v8[5]];
    const float* g_c    = (const float*)d_in[v8[6]];
    const float* b_c    = (const float*)d_in[v8[7]];

    float* sc = nullptr;
    cudaGetSymbolAddress((void**)&sc, g_scratch);

    float* out       = (float*)d_out;            // [T,B,D]
    float* out_hid   = out + kTBD;               // [B,D]
    float* out_pattn = out_hid + (long)kB * kD;  // [T,B,S]

    cudaFuncSetAttribute(gemm_mma_kernel,
                         cudaFuncAttributeMaxDynamicSharedMemorySize, GEMM_SMEM);

    dim3 tb(32, 8);
    const float invsq = rsqrtf((float)kD);

    // 0) weight transposes (-> K-major [N,K], rounded tf32)
    transpose_kernel<<<dim3(48, 16, 1), tb>>>(W_in,  sc + OF_WTIN,  kD, 3 * kD, 0, 0);
    transpose_kernel<<<dim3(16, 16, 1), tb>>>(W_enc, sc + OF_WTENC, kD, kD, 0, 0);
    transpose_kernel<<<dim3(16, 16, 1), tb>>>(W_att, sc + OF_WTATT, kD, kD, 0, 0);
    transpose_kernel<<<dim3(16, 16, 1), tb>>>(W_hid, sc + OF_WTHID, kD, kD, 0, 0);
    transpose_kernel<<<dim3(16, 16, 1), tb>>>(W_ctx, sc + OF_WTCTX, kD, kD, 0, 0);

    // 1) preact = prev @ W_in        [16384 x 1536]
    gemm_mma_kernel<<<dim3(12, 128, 1), 256, GEMM_SMEM>>>(
        prev, sc + OF_WTIN, sc + OF_PRE, 512, 512, 512, 1536, 0, 0, 0, 1.f);
    // 2) LN(3D) + split + sigmoid
    ln_preact_kernel<<<(unsigned)kTB, 384>>>(sc + OF_PRE, g_pre, b_pre,
                                             sc + OF_Z, sc + OF_HG, sc + OF_PL);
    // 3) pctx = LN(enc @ W_enc)
    gemm_mma_kernel<<<dim3(4, 128, 1), 256, GEMM_SMEM>>>(
        enc, sc + OF_WTENC, sc + OF_PCTX, 512, 512, 512, 512, 0, 0, 0, 1.f);
    ln512_kernel<<<(unsigned)kTB, 128>>>(sc + OF_PCTX, g_enc, b_enc);
    // 3b) pctxT[b] = pctx[b]^T  ([S,D] -> [D,S])
    transpose_kernel<<<dim3(16, 16, 32), tb>>>(sc + OF_PCTX, sc + OF_PCTXT,
                                               kS, kD, (long)kS * kD, (long)kD * kS);
    // 4) SRU scan
    scan_kernel<<<(kB * kD) / 256, 256>>>(sc + OF_Z, sc + OF_PL, hidden, sc + OF_SS);
    // 5) attn_in = LN(ss @ W_attn)
    gemm_mma_kernel<<<dim3(4, 128, 1), 256, GEMM_SMEM>>>(
        sc + OF_SS, sc + OF_WTATT, sc + OF_ATT, 512, 512, 512, 512, 0, 0, 0, 1.f);
    ln512_kernel<<<(unsigned)kTB, 128>>>(sc + OF_ATT, g_att, b_att);
    // 6) align[b] = attn_in_b [T,D] @ pctx_b[S,D]^T   (batched NT)
    gemm_mma_kernel<<<dim3(4, 4, 32), 256, GEMM_SMEM>>>(
        sc + OF_ATT, sc + OF_PCTX, sc + OF_AV, 512,
        (long)kB * kD, 512, 512, kD, (long)kS * kD, (long)kT * kS, 1.f);
    // 7) masked softmax
    softmax_kernel<<<(unsigned)(kB * kT), 128>>>(sc + OF_AV, out_pattn, mlen);
    // 8) attn_out = (av @ pctx) / sqrt(D)  via av[T,S] @ pctxT[D,S]^T
    gemm_mma_kernel<<<dim3(4, 4, 32), 256, GEMM_SMEM>>>(
        sc + OF_AV, sc + OF_PCTXT, sc + OF_AO, 512,
        512, 512, (long)kB * kD, (long)kT * kS, (long)kD * kS, kD, invsq);
    // 9) h1 = ss @ W_hidden ; h2 = attn_out @ W_ctx
    gemm_mma_kernel<<<dim3(4, 128, 1), 256, GEMM_SMEM>>>(
        sc + OF_SS, sc + OF_WTHID, sc + OF_H1, 512, 512, 512, 512, 0, 0, 0, 1.f);
    gemm_mma_kernel<<<dim3(4, 128, 1), 256, GEMM_SMEM>>>(
        sc + OF_AO, sc + OF_WTCTX, sc + OF_H2, 512, 512, 512, 512, 0, 0, 0, 1.f);
    // 10) final blend
    final_kernel<<<(unsigned)kTB, 128>>>(sc + OF_H1, sc + OF_H2, sc + OF_HG, prev,
                                         g_h, b_h, g_c, b_c, out);
    // 11) hidden_last = ss[T-1]
    cudaMemcpyAsync(out_hid, sc + OF_SS + (long)(kT - 1) * kB * kD,
                    (size_t)kB * kD * sizeof(float), cudaMemcpyDeviceToDevice, 0);
}

// round 5
// speedup vs baseline: 3.1718x; 1.0925x over previous
#include <cuda_runtime.h>
#include <math.h>
#include <stdint.h>

// ---------------------------------------------------------------------------
// AttSRU: T=512, B=32, S=512, D=512, fp32.
// Round 4: mma.sync tf32 GEMM with ldmatrix fragment loads + 3-stage cp.async.
// ---------------------------------------------------------------------------

namespace {
constexpr int  kT = 512, kB = 32, kS = 512, kD = 512;
constexpr long kTB   = (long)kT * kB;      // 16384 rows
constexpr long kTBD  = kTB * kD;           // 8388608
constexpr long kPRE  = kTB * 3 * kD;       // 25165824
constexpr float kEPS = 1e-6f;

// scratch layout (single __device__ array)
constexpr long OF_PRE   = 0;                 // [TB, 3D] raw preact
constexpr long OF_Z     = kPRE;              // [T,B,D] sigmoid(z)
constexpr long OF_HG    = OF_Z    + kTBD;    // [T,B,D] sigmoid(h_gate)
constexpr long OF_PL    = OF_HG   + kTBD;    // [T,B,D] pl_t
constexpr long OF_PCTX  = OF_PL   + kTBD;    // [B,S,D] LN(enc@W_enc)
constexpr long OF_SS    = OF_PCTX + kTBD;    // [T,B,D] scan states
constexpr long OF_ATT   = OF_SS   + kTBD;    // [T,B,D] LN(ss@W_attn)
constexpr long OF_AV    = OF_ATT  + kTBD;    // [B,T,S] align -> softmax
constexpr long OF_AO    = OF_AV   + kTBD;    // [T,B,D] attn_out
constexpr long OF_H1    = OF_AO   + kTBD;    // [TB,D]
constexpr long OF_H2    = OF_H1   + kTBD;    // [TB,D]
constexpr long OF_PCTXT = OF_H2   + kTBD;    // [B,D,S] pctx transposed
constexpr long OF_WTIN  = OF_PCTXT + kTBD;   // [3D,D]
constexpr long OF_WTENC = OF_WTIN  + (long)3 * kD * kD;
constexpr long OF_WTATT = OF_WTENC + (long)kD * kD;
constexpr long OF_WTHID = OF_WTATT + (long)kD * kD;
constexpr long OF_WTCTX = OF_WTHID + (long)kD * kD;
constexpr long kSCRATCH = OF_WTCTX + (long)kD * kD;

// GEMM smem: row stride 36 floats (conflict-free ldmatrix/cp.async, 16B align)
constexpr int RS = 36;                        // floats per smem row
constexpr int OP_FLOATS = 128 * RS;           // one operand per stage
constexpr int STAGE_FLOATS = 2 * OP_FLOATS;   // A + B
constexpr int GEMM_SMEM = 3 * STAGE_FLOATS * 4;   // 3 stages -> 110592 B
}

__device__ float g_scratch[kSCRATCH];

// ---------------------------------------------------------------------------
// Helpers
// ---------------------------------------------------------------------------
__device__ __forceinline__ float warpSum(float v) {
#pragma unroll
    for (int o = 16; o; o >>= 1) v += __shfl_xor_sync(0xffffffffu, v, o);
    return v;
}
__device__ __forceinline__ float warpMax(float v) {
#pragma unroll
    for (int o = 16; o; o >>= 1) v = fmaxf(v, __shfl_xor_sync(0xffffffffu, v, o));
    return v;
}
__device__ __forceinline__ float blockSum(float v, float* sh) {
    int w = threadIdx.x >> 5, l = threadIdx.x & 31, nw = blockDim.x >> 5;
    v = warpSum(v);
    if (l == 0) sh[w] = v;
    __syncthreads();
    v = (l < nw) ? sh[l] : 0.f;
    v = warpSum(v);
    __syncthreads();
    return v;
}
__device__ __forceinline__ float blockMax(float v, float* sh) {
    int w = threadIdx.x >> 5, l = threadIdx.x & 31, nw = blockDim.x >> 5;
    v = warpMax(v);
    if (l == 0) sh[w] = v;
    __syncthreads();
    v = (l < nw) ? sh[l] : -INFINITY;
    v = warpMax(v);
    __syncthreads();
    return v;
}
__device__ __forceinline__ float sigm(float x) { return 1.f / (1.f + expf(-x)); }
// round-to-nearest tf32 (kills truncation bias in the tensor unit)
__device__ __forceinline__ float tf32r(float x) {
    uint32_t u;
    asm("cvt.rna.tf32.f32 %0, %1;" : "=r"(u) : "f"(x));
    return __uint_as_float(u);
}

__device__ __forceinline__ void ldsm4(uint32_t& r0, uint32_t& r1,
                                      uint32_t& r2, uint32_t& r3, uint32_t addr) {
    asm volatile("ldmatrix.sync.aligned.m8n8.x4.shared.b16 {%0,%1,%2,%3}, [%4];"
                 : "=r"(r0), "=r"(r1), "=r"(r2), "=r"(r3) : "r"(addr));
}

// ---------------------------------------------------------------------------
// tf32 mma.sync GEMM: C[M,N] = alpha * A[M,K] @ B[N,K]^T   (NT form)
// A, B fp32 row-major K-major (lda/ldb = element row strides).
// M%128==0, N%128==0, K%32==0. Batched via blockIdx.z strides.
// Grid: (N/128, M/128, batch). Block: 256 (8 warps, 4x2, warp tile 32x64).
// ---------------------------------------------------------------------------
__global__ __launch_bounds__(256, 2)
void gemm_mma_kernel(const float* __restrict__ A, const float* __restrict__ B,
                     float* __restrict__ C, int K,
                     long lda, long ldb, long ldc,
                     long sA, long sB, long sC, float alpha)
{
    extern __shared__ float smem[];
    const uint32_t sb = (uint32_t)__cvta_generic_to_shared(smem);
    A += (long)blockIdx.z * sA;
    B += (long)blockIdx.z * sB;
    C += (long)blockIdx.z * sC;
    const int bm = blockIdx.y * 128, bn = blockIdx.x * 128;
    const int tid = threadIdx.x, wid = tid >> 5, lane = tid & 31;
    const int mw = (wid >> 1) * 32;        // warp m offset in tile
    const int nw = (wid & 1) * 64;         // warp n offset in tile
    const int lr = lane >> 2;              // 0..7
    const int lc = lane & 3;               // 0..3
    const int mI = lane >> 3;              // ldmatrix matrix index 0..3
    const int rowo = lane & 7;

    // ldmatrix per-lane source offsets (floats, within a stage)
    // A frag (m16 tile at row R0): mats {r, r+8, c+4 variants}
    const int aoff = (mw + (mI & 1) * 8 + rowo) * RS + (mI >> 1) * 4;
    // B frag pair p (two n8 tiles at nw+p*16): mats {n, n|c+4, n+8, n+8|c+4}
    int boff[4];
#pragma unroll
    for (int p = 0; p < 4; p++)
        boff[p] = OP_FLOATS + (nw + p * 16 + (mI >> 1) * 8 + rowo) * RS + (mI & 1) * 4;

    // cp.async slot mapping: 4 float4 per thread per operand
    int rowi[4], qi[4];
#pragma unroll
    for (int t = 0; t < 4; t++) {
        int id = tid + t * 256;            // 0..1023
        rowi[t] = id >> 3;
        qi[t]   = id & 7;
    }
    const int nch = K >> 5;                // K/32 chunks

    auto load_chunk = [&](int c, int s) {
        float* As = smem + s * STAGE_FLOATS;
        float* Bs = As + OP_FLOATS;
        long ko = (long)c * 32;
#pragma unroll
        for (int t = 0; t < 4; t++) {
            const float* ga = A + (long)(bm + rowi[t]) * lda + ko + qi[t] * 4;
            float* da = As + rowi[t] * RS + qi[t] * 4;
            asm volatile("cp.async.cg.shared.global [%0], [%1], 16;"
                         :: "r"((uint32_t)__cvta_generic_to_shared(da)), "l"(ga));
        }
#pragma unroll
        for (int t = 0; t < 4; t++) {
            const float* gb = B + (long)(bn + rowi[t]) * ldb + ko + qi[t] * 4;
            float* db = Bs + rowi[t] * RS + qi[t] * 4;
            asm volatile("cp.async.cg.shared.global [%0], [%1], 16;"
                         :: "r"((uint32_t)__cvta_generic_to_shared(db)), "l"(gb));
        }
    };

    float acc[2][8][4];
#pragma unroll
    for (int i = 0; i < 2; i++)
#pragma unroll
        for (int j = 0; j < 8; j++)
#pragma unroll
            for (int v = 0; v < 4; v++) acc[i][j][v] = 0.f;

    load_chunk(0, 0);
    asm volatile("cp.async.commit_group;");
    if (nch > 1) {
        load_chunk(1, 1);
        asm volatile("cp.async.commit_group;");
    }

    for (int c = 0; c < nch; c++) {
        if (c + 2 < nch) {
            load_chunk(c + 2, (c + 2) % 3);     // stage of chunk c-1 (drained)
            asm volatile("cp.async.commit_group;");
            asm volatile("cp.async.wait_group 2;");
        } else if (c + 1 < nch) {
            asm volatile("cp.async.wait_group 1;");
        } else {
            asm volatile("cp.async.wait_group 0;");
        }
        __syncthreads();
        const uint32_t stb = sb + (uint32_t)((c % 3) * STAGE_FLOATS) * 4u;
#pragma unroll
        for (int kk = 0; kk < 4; kk++) {
            const uint32_t kb = (uint32_t)(kk * 8) * 4u;
            uint32_t a[2][4];
#pragma unroll
            for (int im = 0; im < 2; im++)
                ldsm4(a[im][0], a[im][1], a[im][2], a[im][3],
                      stb + (uint32_t)(aoff + im * 16 * RS) * 4u + kb);
#pragma unroll
            for (int p = 0; p < 4; p++) {
                uint32_t b0, b1, b2, b3;
                ldsm4(b0, b1, b2, b3, stb + (uint32_t)boff[p] * 4u + kb);
#pragma unroll
                for (int im = 0; im < 2; im++) {
                    asm volatile(
                        "mma.sync.aligned.m16n8k8.row.col.f32.tf32.tf32.f32 "
                        "{%0,%1,%2,%3}, {%4,%5,%6,%7}, {%8,%9}, {%0,%1,%2,%3};"
                        : "+f"(acc[im][2 * p][0]), "+f"(acc[im][2 * p][1]),
                          "+f"(acc[im][2 * p][2]), "+f"(acc[im][2 * p][3])
                        : "r"(a[im][0]), "r"(a[im][1]), "r"(a[im][2]), "r"(a[im][3]),
                          "r"(b0), "r"(b1));
                    asm volatile(
                        "mma.sync.aligned.m16n8k8.row.col.f32.tf32.tf32.f32 "
                        "{%0,%1,%2,%3}, {%4,%5,%6,%7}, {%8,%9}, {%0,%1,%2,%3};"
                        : "+f"(acc[im][2 * p + 1][0]), "+f"(acc[im][2 * p + 1][1]),
                          "+f"(acc[im][2 * p + 1][2]), "+f"(acc[im][2 * p + 1][3])
                        : "r"(a[im][0]), "r"(a[im][1]), "r"(a[im][2]), "r"(a[im][3]),
                          "r"(b2), "r"(b3));
                }
            }
        }
        __syncthreads();
    }

    // epilogue: direct float2 stores
#pragma unroll
    for (int im = 0; im < 2; im++) {
        long r0 = (long)(bm + mw + im * 16 + lr);
#pragma unroll
        for (int jn = 0; jn < 8; jn++) {
            long col = bn + nw + jn * 8 + lc * 2;
            float2 v0 = make_float2(acc[im][jn][0] * alpha, acc[im][jn][1] * alpha);
            float2 v1 = make_float2(acc[im][jn][2] * alpha, acc[im][jn][3] * alpha);
            *reinterpret_cast<float2*>(C + r0 * ldc + col) = v0;
            *reinterpret_cast<float2*>(C + (r0 + 8) * ldc + col) = v1;
        }
    }
}

// ---------------------------------------------------------------------------
// Transpose: in [R,C] -> out [C,R], output rounded to tf32 (RNA).
// blockDim (32,8), grid (C_tiles, R_tiles, batch).
// ---------------------------------------------------------------------------
__global__ void transpose_kernel(const float* __restrict__ in, float* __restrict__ out,
                                 int R, int C, long sIn, long sOut)
{
    __shared__ float t[32][33];
    in  += (long)blockIdx.z * sIn;
    out += (long)blockIdx.z * sOut;
    int bx = blockIdx.x * 32, by = blockIdx.y * 32;
    int x = threadIdx.x, y = threadIdx.y;
#pragma unroll
    for (int i = 0; i < 32; i += 8) t[y + i][x] = in[(long)(by + y + i) * C + bx + x];
    __syncthreads();
#pragma unroll
    for (int i = 0; i < 32; i += 8)
        out[(long)(bx + y + i) * R + by + x] = tf32r(t[x][y + i]);
}

// 4 x [512,512] weight transposes in one launch (z selects the weight)
__global__ void transpose4_kernel(const float* __restrict__ w0, const float* __restrict__ w1,
                                  const float* __restrict__ w2, const float* __restrict__ w3,
                                  float* __restrict__ o0, float* __restrict__ o1,
                                  float* __restrict__ o2, float* __restrict__ o3)
{
    __shared__ float t[32][33];
    const float* in; float* out;
    switch (blockIdx.z) {
        case 0: in = w0; out = o0; break;
        case 1: in = w1; out = o1; break;
        case 2: in = w2; out = o2; break;
        default: in = w3; out = o3; break;
    }
    int bx = blockIdx.x * 32, by = blockIdx.y * 32;
    int x = threadIdx.x, y = threadIdx.y;
#pragma unroll
    for (int i = 0; i < 32; i += 8) t[y + i][x] = in[(long)(by + y + i) * kD + bx + x];
    __syncthreads();
#pragma unroll
    for (int i = 0; i < 32; i += 8)
        out[(long)(bx + y + i) * kD + by + x] = tf32r(t[x][y + i]);
}

// ---------------------------------------------------------------------------
// LN over 3D=1536, split + sigmoid into Z / HG / PL. block=384, grid=TB.
// ---------------------------------------------------------------------------
__global__ void ln_preact_kernel(const float* __restrict__ pre,
                                 const float* __restrict__ g, const float* __restrict__ bb,
                                 float* __restrict__ Z, float* __restrict__ HG,
                                 float* __restrict__ PL)
{
    __shared__ float sh[32];
    long row = blockIdx.x;
    int c = threadIdx.x * 4;
    const float* r = pre + row * (3 * kD);
    float4 v = *reinterpret_cast<const float4*>(r + c);
    float s = v.x + v.y + v.z + v.w;
    float q = v.x * v.x + v.y * v.y + v.z * v.z + v.w * v.w;
    s = blockSum(s, sh);
    q = blockSum(q, sh);
    const float invW = 1.f / (3 * kD);
    float m  = s * invW;
    float rv = rsqrtf(q * invW - m * m + kEPS);
    float n0 = g[c + 0] * ((v.x - m) * rv) + bb[c + 0];
    float n1 = g[c + 1] * ((v.y - m) * rv) + bb[c + 1];
    float n2 = g[c + 2] * ((v.z - m) * rv) + bb[c + 2];
    float n3 = g[c + 3] * ((v.w - m) * rv) + bb[c + 3];
    long rD = row * kD;
    if (c < kD) {
        float4 o = make_float4(sigm(n0), sigm(n1), sigm(n2), sigm(n3));
        *reinterpret_cast<float4*>(Z + rD + c) = o;
    } else if (c < 2 * kD) {
        float4 o = make_float4(sigm(n0), sigm(n1), sigm(n2), sigm(n3));
        *reinterpret_cast<float4*>(HG + rD + (c - kD)) = o;
    } else {
        float4 o = make_float4(n0, n1, n2, n3);
        *reinterpret_cast<float4*>(PL + rD + (c - 2 * kD)) = o;
    }
}

// In-place LN over D=512, output rounded to tf32. block=128, grid=rows.
__global__ void ln512_kernel(float* __restrict__ x,
                             const float* __restrict__ g, const float* __restrict__ b)
{
    __shared__ float sh[32];
    long row = blockIdx.x;
    int c = threadIdx.x * 4;
    float* r = x + row * kD;
    float4 v = *reinterpret_cast<const float4*>(r + c);
    float s = v.x + v.y + v.z + v.w;
    float q = v.x * v.x + v.y * v.y + v.z * v.z + v.w * v.w;
    s = blockSum(s, sh);
    q = blockSum(q, sh);
    const float invW = 1.f / kD;
    float m  = s * invW;
    float rv = rsqrtf(q * invW - m * m + kEPS);
    v.x = tf32r(g[c + 0] * ((v.x - m) * rv) + b[c + 0]);
    v.y = tf32r(g[c + 1] * ((v.y - m) * rv) + b[c + 1]);
    v.z = tf32r(g[c + 2] * ((v.z - m) * rv) + b[c + 2]);
    v.w = tf32r(g[c + 3] * ((v.w - m) * rv) + b[c + 3]);
    *reinterpret_cast<float4*>(r + c) = v;
}

// SRU linear recurrence
__global__ void scan_kernel(const float* __restrict__ Z, const float* __restrict__ PL,
                            const float* __restrict__ h0, float* __restrict__ ss)
{
    int idx = blockIdx.x * blockDim.x + threadIdx.x;   // b*D + d
    float s = h0[idx];
    long off = idx;
    const long stride = (long)kB * kD;
    for (int t = 0; t < kT; t++) {
        float z = Z[off];
        float p = PL[off];
        s = (1.f - z) * s + z * p;
        ss[off] = s;
        off += stride;
    }
}

// Masked softmax over S=512; rounded probs into av (GEMM operand),
// exact probs into p_attn output.
__global__ void softmax_kernel(float* __restrict__ av, float* __restrict__ pattn,
                               const int* __restrict__ mlen)
{
    __shared__ float sh[32];
    long row = blockIdx.x;                 // b*T + t
    int b = (int)(row / kT), t = (int)(row % kT);
    int ml = mlen[b];
    float* r = av + row * kS;
    int c = threadIdx.x * 4;
    float4 v = *reinterpret_cast<const float4*>(r + c);
    const float inv = rsqrtf((float)kD);
    float x0 = v.x * inv, x1 = v.y * inv, x2 = v.z * inv, x3 = v.w * inv;
    float mx = -INFINITY;
    if (c + 0 < ml) mx = fmaxf(mx, x0);
    if (c + 1 < ml) mx = fmaxf(mx, x1);
    if (c + 2 < ml) mx = fmaxf(mx, x2);
    if (c + 3 < ml) mx = fmaxf(mx, x3);
    mx = blockMax(mx, sh);
    float e0 = (c + 0 < ml) ? expf(x0 - mx) : 0.f;
    float e1 = (c + 1 < ml) ? expf(x1 - mx) : 0.f;
    float e2 = (c + 2 < ml) ? expf(x2 - mx) : 0.f;
    float e3 = (c + 3 < ml) ? expf(x3 - mx) : 0.f;
    float sum = blockSum(e0 + e1 + e2 + e3, sh);
    float is = 1.f / sum;
    float4 o = make_float4(e0 * is, e1 * is, e2 * is, e3 * is);
    *reinterpret_cast<float4*>(pattn + ((long)t * kB + b) * kS + c) = o;
    float4 oq = make_float4(tf32r(o.x), tf32r(o.y), tf32r(o.z), tf32r(o.w));
    *reinterpret_cast<float4*>(r + c) = oq;
}

// out = (1-hg)*tanh(LN(h1)+LN(h2)) + hg*prev
__global__ void final_kernel(const float* __restrict__ h1, const float* __restrict__ h2,
                             const float* __restrict__ HG, const float* __restrict__ prev,
                             const float* __restrict__ g_h, const float* __restrict__ b_h,
                             const float* __restrict__ g_c, const float* __restrict__ b_c,
                             float* __restrict__ out)
{
    __shared__ float sh[32];
    long row = blockIdx.x;
    int c = threadIdx.x * 4;
    float4 a = *reinterpret_cast<const float4*>(h1 + row * kD + c);
    float4 d = *reinterpret_cast<const float4*>(h2 + row * kD + c);
    float s1 = a.x + a.y + a.z + a.w;
    float q1 = a.x * a.x + a.y * a.y + a.z * a.z + a.w * a.w;
    float s2 = d.x + d.y + d.z + d.w;
    float q2 = d.x * d.x + d.y * d.y + d.z * d.z + d.w * d.w;
    s1 = blockSum(s1, sh);
    q1 = blockSum(q1, sh);
    s2 = blockSum(s2, sh);
    q2 = blockSum(q2, sh);
    const float invW = 1.f / kD;
    float m1 = s1 * invW, r1 = rsqrtf(q1 * invW - m1 * m1 + kEPS);
    float m2 = s2 * invW, r2 = rsqrtf(q2 * invW - m2 * m2 + kEPS);
    float4 hg = *reinterpret_cast<const float4*>(HG + row * kD + c);
    float4 pv = *reinterpret_cast<const float4*>(prev + row * kD + c);
    float t0 = tanhf(g_h[c + 0] * ((a.x - m1) * r1) + b_h[c + 0] +
                     g_c[c + 0] * ((d.x - m2) * r2) + b_c[c + 0]);
    float t1 = tanhf(g_h[c + 1] * ((a.y - m1) * r1) + b_h[c + 1] +
                     g_c[c + 1] * ((d.y - m2) * r2) + b_c[c + 1]);
    float t2 = tanhf(g_h[c + 2] * ((a.z - m1) * r1) + b_h[c + 2] +
                     g_c[c + 2] * ((d.z - m2) * r2) + b_c[c + 2]);
    float t3 = tanhf(g_h[c + 3] * ((a.w - m1) * r1) + b_h[c + 3] +
                     g_c[c + 3] * ((d.w - m2) * r2) + b_c[c + 3]);
    float4 o;
    o.x = (1.f - hg.x) * t0 + hg.x * pv.x;
    o.y = (1.f - hg.y) * t1 + hg.y * pv.y;
    o.z = (1.f - hg.z) * t2 + hg.z * pv.z;
    o.w = (1.f - hg.w) * t3 + hg.w * pv.w;
    *reinterpret_cast<float4*>(out + row * kD + c) = o;
}

// ---------------------------------------------------------------------------
// Launch
// ---------------------------------------------------------------------------
extern "C" void kernel_launch(void* const* d_in, const int* in_sizes, int n_in,
                              void* d_out, int out_size)
{
    int i_prev = -1, i_enc = -1, i_hidden = -1, i_ml = -1, i_Win = -1;
    int w4[4] = {-1, -1, -1, -1}; int n4 = 0;
    int p2[2] = {-1, -1};         int np = 0;
    int v8[8] = {-1, -1, -1, -1, -1, -1, -1, -1}; int nv = 0;
    for (int i = 0; i < n_in; i++) {
        switch (in_sizes[i]) {
            case 8388608: if (i_prev < 0) i_prev = i; else i_enc = i; break;
            case 16384:   i_hidden = i; break;
            case 32:      i_ml = i; break;
            case 786432:  i_Win = i; break;
            case 262144:  if (n4 < 4) w4[n4++] = i; break;
            case 1536:    if (np < 2) p2[np++] = i; break;
            case 512:     if (nv < 8) v8[nv++] = i; break;
            default: break;
        }
    }
    const float* prev   = (const float*)d_in[i_prev];
    const float* hidden = (const float*)d_in[i_hidden];
    const float* enc    = (const float*)d_in[i_enc];
    const int*   mlen   = (const int*)d_in[i_ml];
    const float* W_in   = (const float*)d_in[i_Win];
    const float* W_enc  = (const float*)d_in[w4[0]];
    const float* W_att  = (const float*)d_in[w4[1]];
    const float* W_hid  = (const float*)d_in[w4[2]];
    const float* W_ctx  = (const float*)d_in[w4[3]];
    const float* g_pre  = (const float*)d_in[p2[0]];
    const float* b_pre  = (const float*)d_in[p2[1]];
    const float* g_enc  = (const float*)d_in[v8[0]];
    const float* b_enc  = (const float*)d_in[v8[1]];
    const float* g_att  = (const float*)d_in[v8[2]];
    const float* b_att  = (const float*)d_in[v8[3]];
    const float* g_h    = (const float*)d_in[v8[4]];
    const float* b_h    = (const float*)d_in[v8[5]];
    const float* g_c    = (const float*)d_in[v8[6]];
    const float* b_c    = (const float*)d_in[v8[7]];

    float* sc = nullptr;
    cudaGetSymbolAddress((void**)&sc, g_scratch);

    float* out       = (float*)d_out;            // [T,B,D]
    float* out_hid   = out + kTBD;               // [B,D]
    float* out_pattn = out_hid + (long)kB * kD;  // [T,B,S]

    cudaFuncSetAttribute(gemm_mma_kernel,
                         cudaFuncAttributeMaxDynamicSharedMemorySize, GEMM_SMEM);

    dim3 tb(32, 8);
    const float invsq = rsqrtf((float)kD);

    // 0) weight transposes (-> K-major [N,K], rounded tf32)
    transpose_kernel<<<dim3(16, 16, 3), tb>>>(W_in, sc + OF_WTIN, kD, 3 * kD,
                                              512, (long)kD * kD);
    transpose4_kernel<<<dim3(16, 16, 4), tb>>>(W_enc, W_att, W_hid, W_ctx,
                                               sc + OF_WTENC, sc + OF_WTATT,
                                               sc + OF_WTHID, sc + OF_WTCTX);

    // 1) preact = prev @ W_in        [16384 x 1536]
    gemm_mma_kernel<<<dim3(12, 128, 1), 256, GEMM_SMEM>>>(
        prev, sc + OF_WTIN, sc + OF_PRE, 512, 512, 512, 1536, 0, 0, 0, 1.f);
    // 2) LN(3D) + split + sigmoid
    ln_preact_kernel<<<(unsigned)kTB, 384>>>(sc + OF_PRE, g_pre, b_pre,
                                             sc + OF_Z, sc + OF_HG, sc + OF_PL);
    // 3) pctx = LN(enc @ W_enc)
    gemm_mma_kernel<<<dim3(4, 128, 1), 256, GEMM_SMEM>>>(
        enc, sc + OF_WTENC, sc + OF_PCTX, 512, 512, 512, 512, 0, 0, 0, 1.f);
    ln512_kernel<<<(unsigned)kTB, 128>>>(sc + OF_PCTX, g_enc, b_enc);
    // 3b) pctxT[b] = pctx[b]^T  ([S,D] -> [D,S])
    transpose_kernel<<<dim3(16, 16, 32), tb>>>(sc + OF_PCTX, sc + OF_PCTXT,
                                               kS, kD, (long)kS * kD, (long)kD * kS);
    // 4) SRU scan
    scan_kernel<<<(kB * kD) / 256, 256>>>(sc + OF_Z, sc + OF_PL, hidden, sc + OF_SS);
    // 5) attn_in = LN(ss @ W_attn)
    gemm_mma_kernel<<<dim3(4, 128, 1), 256, GEMM_SMEM>>>(
        sc + OF_SS, sc + OF_WTATT, sc + OF_ATT, 512, 512, 512, 512, 0, 0, 0, 1.f);
    ln512_kernel<<<(unsigned)kTB, 128>>>(sc + OF_ATT, g_att, b_att);
    // 6) align[b] = attn_in_b [T,D] @ pctx_b[S,D]^T   (batched NT)
    gemm_mma_kernel<<<dim3(4, 4, 32), 256, GEMM_SMEM>>>(
        sc + OF_ATT, sc + OF_PCTX, sc + OF_AV, 512,
        (long)kB * kD, 512, 512, kD, (long)kS * kD, (long)kT * kS, 1.f);
    // 7) masked softmax
    softmax_kernel<<<(unsigned)(kB * kT), 128>>>(sc + OF_AV, out_pattn, mlen);
    // 8) attn_out = (av @ pctx) / sqrt(D)  via av[T,S] @ pctxT[D,S]^T
    gemm_mma_kernel<<<dim3(4, 4, 32), 256, GEMM_SMEM>>>(
        sc + OF_AV, sc + OF_PCTXT, sc + OF_AO, 512,
        512, 512, (long)kB * kD, (long)kT * kS, (long)kD * kS, kD, invsq);
    // 9) h1 = ss @ W_hidden ; h2 = attn_out @ W_ctx
    gemm_mma_kernel<<<dim3(4, 128, 1), 256, GEMM_SMEM>>>(
        sc + OF_SS, sc + OF_WTHID, sc + OF_H1, 512, 512, 512, 512, 0, 0, 0, 1.f);
    gemm_mma_kernel<<<dim3(4, 128, 1), 256, GEMM_SMEM>>>(
        sc + OF_AO, sc + OF_WTCTX, sc + OF_H2, 512, 512, 512, 512, 0, 0, 0, 1.f);
    // 10) final blend
    final_kernel<<<(unsigned)kTB, 128>>>(sc + OF_H1, sc + OF_H2, sc + OF_HG, prev,
                                         g_h, b_h, g_c, b_c, out);
    // 11) hidden_last = ss[T-1]
    cudaMemcpyAsync(out_hid, sc + OF_SS + (long)(kT - 1) * kB * kD,
                    (size_t)kB * kD * sizeof(float), cudaMemcpyDeviceToDevice, 0);
}

// round 8
// speedup vs baseline: 3.2566x; 1.0267x over previous
#include <cuda_runtime.h>
#include <math.h>
#include <stdint.h>

// ---------------------------------------------------------------------------
// AttSRU: T=512, B=32, S=512, D=512, fp32.
// Round 6: batched-prefetch scan (MLP fix), single-sync GEMM mainloop,
// two-stream overlap of the enc chain and h1 GEMM.
// ---------------------------------------------------------------------------

namespace {
constexpr int  kT = 512, kB = 32, kS = 512, kD = 512;
constexpr long kTB   = (long)kT * kB;      // 16384 rows
constexpr long kTBD  = kTB * kD;           // 8388608
constexpr long kPRE  = kTB * 3 * kD;       // 25165824
constexpr float kEPS = 1e-6f;

// scratch layout (single __device__ array)
constexpr long OF_PRE   = 0;                 // [TB, 3D] raw preact
constexpr long OF_Z     = kPRE;              // [T,B,D] sigmoid(z)
constexpr long OF_HG    = OF_Z    + kTBD;    // [T,B,D] sigmoid(h_gate)
constexpr long OF_PL    = OF_HG   + kTBD;    // [T,B,D] pl_t
constexpr long OF_PCTX  = OF_PL   + kTBD;    // [B,S,D] LN(enc@W_enc)
constexpr long OF_SS    = OF_PCTX + kTBD;    // [T,B,D] scan states
constexpr long OF_ATT   = OF_SS   + kTBD;    // [T,B,D] LN(ss@W_attn)
constexpr long OF_AV    = OF_ATT  + kTBD;    // [B,T,S] align -> softmax
constexpr long OF_AO    = OF_AV   + kTBD;    // [T,B,D] attn_out
constexpr long OF_H1    = OF_AO   + kTBD;    // [TB,D]
constexpr long OF_H2    = OF_H1   + kTBD;    // [TB,D]
constexpr long OF_PCTXT = OF_H2   + kTBD;    // [B,D,S] pctx transposed
constexpr long OF_WTIN  = OF_PCTXT + kTBD;   // [3D,D]
constexpr long OF_WTENC = OF_WTIN  + (long)3 * kD * kD;
constexpr long OF_WTATT = OF_WTENC + (long)kD * kD;
constexpr long OF_WTHID = OF_WTATT + (long)kD * kD;
constexpr long OF_WTCTX = OF_WTHID + (long)kD * kD;
constexpr long kSCRATCH = OF_WTCTX + (long)kD * kD;

// GEMM smem: row stride 36 floats (conflict-free ldmatrix/cp.async, 16B align)
constexpr int RS = 36;                        // floats per smem row
constexpr int OP_FLOATS = 128 * RS;           // one operand per stage
constexpr int STAGE_FLOATS = 2 * OP_FLOATS;   // A + B
constexpr int GEMM_SMEM = 3 * STAGE_FLOATS * 4;   // 3 stages -> 110592 B
}

__device__ float g_scratch[kSCRATCH];

// ---------------------------------------------------------------------------
// Helpers
// ---------------------------------------------------------------------------
__device__ __forceinline__ float warpSum(float v) {
#pragma unroll
    for (int o = 16; o; o >>= 1) v += __shfl_xor_sync(0xffffffffu, v, o);
    return v;
}
__device__ __forceinline__ float warpMax(float v) {
#pragma unroll
    for (int o = 16; o; o >>= 1) v = fmaxf(v, __shfl_xor_sync(0xffffffffu, v, o));
    return v;
}
__device__ __forceinline__ float blockSum(float v, float* sh) {
    int w = threadIdx.x >> 5, l = threadIdx.x & 31, nw = blockDim.x >> 5;
    v = warpSum(v);
    if (l == 0) sh[w] = v;
    __syncthreads();
    v = (l < nw) ? sh[l] : 0.f;
    v = warpSum(v);
    __syncthreads();
    return v;
}
__device__ __forceinline__ float blockMax(float v, float* sh) {
    int w = threadIdx.x >> 5, l = threadIdx.x & 31, nw = blockDim.x >> 5;
    v = warpMax(v);
    if (l == 0) sh[w] = v;
    __syncthreads();
    v = (l < nw) ? sh[l] : -INFINITY;
    v = warpMax(v);
    __syncthreads();
    return v;
}
__device__ __forceinline__ float sigm(float x) { return 1.f / (1.f + expf(-x)); }
// round-to-nearest tf32 (kills truncation bias in the tensor unit)
__device__ __forceinline__ float tf32r(float x) {
    uint32_t u;
    asm("cvt.rna.tf32.f32 %0, %1;" : "=r"(u) : "f"(x));
    return __uint_as_float(u);
}

__device__ __forceinline__ void ldsm4(uint32_t& r0, uint32_t& r1,
                                      uint32_t& r2, uint32_t& r3, uint32_t addr) {
    asm volatile("ldmatrix.sync.aligned.m8n8.x4.shared.b16 {%0,%1,%2,%3}, [%4];"
                 : "=r"(r0), "=r"(r1), "=r"(r2), "=r"(r3) : "r"(addr));
}

// ---------------------------------------------------------------------------
// tf32 mma.sync GEMM: C[M,N] = alpha * A[M,K] @ B[N,K]^T   (NT form)
// Grid: (N/128, M/128, batch). Block: 256 (8 warps, 4x2, warp tile 32x64).
// Single __syncthreads per K-chunk: the post-wait barrier proves all warps
// finished compute(c-1), so issuing load(c+2) into stage (c-1)%3 is safe.
// ---------------------------------------------------------------------------
__global__ __launch_bounds__(256, 2)
void gemm_mma_kernel(const float* __restrict__ A, const float* __restrict__ B,
                     float* __restrict__ C, int K,
                     long lda, long ldb, long ldc,
                     long sA, long sB, long sC, float alpha)
{
    extern __shared__ float smem[];
    const uint32_t sb = (uint32_t)__cvta_generic_to_shared(smem);
    A += (long)blockIdx.z * sA;
    B += (long)blockIdx.z * sB;
    C += (long)blockIdx.z * sC;
    const int bm = blockIdx.y * 128, bn = blockIdx.x * 128;
    const int tid = threadIdx.x, wid = tid >> 5, lane = tid & 31;
    const int mw = (wid >> 1) * 32;        // warp m offset in tile
    const int nw = (wid & 1) * 64;         // warp n offset in tile
    const int lr = lane >> 2;              // 0..7
    const int lc = lane & 3;               // 0..3
    const int mI = lane >> 3;              // ldmatrix matrix index 0..3
    const int rowo = lane & 7;

    const int aoff = (mw + (mI & 1) * 8 + rowo) * RS + (mI >> 1) * 4;
    int boff[4];
#pragma unroll
    for (int p = 0; p < 4; p++)
        boff[p] = OP_FLOATS + (nw + p * 16 + (mI >> 1) * 8 + rowo) * RS + (mI & 1) * 4;

    int rowi[4], qi[4];
#pragma unroll
    for (int t = 0; t < 4; t++) {
        int id = tid + t * 256;            // 0..1023
        rowi[t] = id >> 3;
        qi[t]   = id & 7;
    }
    const int nch = K >> 5;                // K/32 chunks

    auto load_chunk = [&](int c, int s) {
        float* As = smem + s * STAGE_FLOATS;
        float* Bs = As + OP_FLOATS;
        long ko = (long)c * 32;
#pragma unroll
        for (int t = 0; t < 4; t++) {
            const float* ga = A + (long)(bm + rowi[t]) * lda + ko + qi[t] * 4;
            float* da = As + rowi[t] * RS + qi[t] * 4;
            asm volatile("cp.async.cg.shared.global [%0], [%1], 16;"
                         :: "r"((uint32_t)__cvta_generic_to_shared(da)), "l"(ga));
        }
#pragma unroll
        for (int t = 0; t < 4; t++) {
            const float* gb = B + (long)(bn + rowi[t]) * ldb + ko + qi[t] * 4;
            float* db = Bs + rowi[t] * RS + qi[t] * 4;
            asm volatile("cp.async.cg.shared.global [%0], [%1], 16;"
                         :: "r"((uint32_t)__cvta_generic_to_shared(db)), "l"(gb));
        }
    };

    float acc[2][8][4];
#pragma unroll
    for (int i = 0; i < 2; i++)
#pragma unroll
        for (int j = 0; j < 8; j++)
#pragma unroll
            for (int v = 0; v < 4; v++) acc[i][j][v] = 0.f;

    load_chunk(0, 0);
    asm volatile("cp.async.commit_group;");
    if (nch > 1) {
        load_chunk(1, 1);
        asm volatile("cp.async.commit_group;");
    }

    for (int c = 0; c < nch; c++) {
        if (c + 1 < nch) asm volatile("cp.async.wait_group 1;");
        else             asm volatile("cp.async.wait_group 0;");
        __syncthreads();
        if (c + 2 < nch) {
            load_chunk(c + 2, (c + 2) % 3);     // stage of chunk c-1 (done)
            asm volatile("cp.async.commit_group;");
        }
        const uint32_t stb = sb + (uint32_t)((c % 3) * STAGE_FLOATS) * 4u;
#pragma unroll
        for (int kk = 0; kk < 4; kk++) {
            const uint32_t kb = (uint32_t)(kk * 8) * 4u;
            uint32_t a[2][4];
#pragma unroll
            for (int im = 0; im < 2; im++)
                ldsm4(a[im][0], a[im][1], a[im][2], a[im][3],
                      stb + (uint32_t)(aoff + im * 16 * RS) * 4u + kb);
#pragma unroll
            for (int p = 0; p < 4; p++) {
                uint32_t b0, b1, b2, b3;
                ldsm4(b0, b1, b2, b3, stb + (uint32_t)boff[p] * 4u + kb);
#pragma unroll
                for (int im = 0; im < 2; im++) {
                    asm volatile(
                        "mma.sync.aligned.m16n8k8.row.col.f32.tf32.tf32.f32 "
                        "{%0,%1,%2,%3}, {%4,%5,%6,%7}, {%8,%9}, {%0,%1,%2,%3};"
                        : "+f"(acc[im][2 * p][0]), "+f"(acc[im][2 * p][1]),
                          "+f"(acc[im][2 * p][2]), "+f"(acc[im][2 * p][3])
                        : "r"(a[im][0]), "r"(a[im][1]), "r"(a[im][2]), "r"(a[im][3]),
                          "r"(b0), "r"(b1));
                    asm volatile(
                        "mma.sync.aligned.m16n8k8.row.col.f32.tf32.tf32.f32 "
                        "{%0,%1,%2,%3}, {%4,%5,%6,%7}, {%8,%9}, {%0,%1,%2,%3};"
                        : "+f"(acc[im][2 * p + 1][0]), "+f"(acc[im][2 * p + 1][1]),
                          "+f"(acc[im][2 * p + 1][2]), "+f"(acc[im][2 * p + 1][3])
                        : "r"(a[im][0]), "r"(a[im][1]), "r"(a[im][2]), "r"(a[im][3]),
                          "r"(b2), "r"(b3));
                }
            }
        }
    }

    // epilogue: direct float2 stores
#pragma unroll
    for (int im = 0; im < 2; im++) {
        long r0 = (long)(bm + mw + im * 16 + lr);
#pragma unroll
        for (int jn = 0; jn < 8; jn++) {
            long col = bn + nw + jn * 8 + lc * 2;
            float2 v0 = make_float2(acc[im][jn][0] * alpha, acc[im][jn][1] * alpha);
            float2 v1 = make_float2(acc[im][jn][2] * alpha, acc[im][jn][3] * alpha);
            *reinterpret_cast<float2*>(C + r0 * ldc + col) = v0;
            *reinterpret_cast<float2*>(C + (r0 + 8) * ldc + col) = v1;
        }
    }
}

// ---------------------------------------------------------------------------
// Transpose: in [R,C] -> out [C,R], output rounded to tf32 (RNA).
// ---------------------------------------------------------------------------
__global__ void transpose_kernel(const float* __restrict__ in, float* __restrict__ out,
                                 int R, int C, long sIn, long sOut)
{
    __shared__ float t[32][33];
    in  += (long)blockIdx.z * sIn;
    out += (long)blockIdx.z * sOut;
    int bx = blockIdx.x * 32, by = blockIdx.y * 32;
    int x = threadIdx.x, y = threadIdx.y;
#pragma unroll
    for (int i = 0; i < 32; i += 8) t[y + i][x] = in[(long)(by + y + i) * C + bx + x];
    __syncthreads();
#pragma unroll
    for (int i = 0; i < 32; i += 8)
        out[(long)(bx + y + i) * R + by + x] = tf32r(t[x][y + i]);
}

// 4 x [512,512] weight transposes in one launch (z selects the weight)
__global__ void transpose4_kernel(const float* __restrict__ w0, const float* __restrict__ w1,
                                  const float* __restrict__ w2, const float* __restrict__ w3,
                                  float* __restrict__ o0, float* __restrict__ o1,
                                  float* __restrict__ o2, float* __restrict__ o3)
{
    __shared__ float t[32][33];
    const float* in; float* out;
    switch (blockIdx.z) {
        case 0: in = w0; out = o0; break;
        case 1: in = w1; out = o1; break;
        case 2: in = w2; out = o2; break;
        default: in = w3; out = o3; break;
    }
    int bx = blockIdx.x * 32, by = blockIdx.y * 32;
    int x = threadIdx.x, y = threadIdx.y;
#pragma unroll
    for (int i = 0; i < 32; i += 8) t[y + i][x] = in[(long)(by + y + i) * kD + bx + x];
    __syncthreads();
#pragma unroll
    for (int i = 0; i < 32; i += 8)
        out[(long)(bx + y + i) * kD + by + x] = tf32r(t[x][y + i]);
}

// ---------------------------------------------------------------------------
// LN over 3D=1536, split + sigmoid into Z / HG / PL. block=384, grid=TB.
// ---------------------------------------------------------------------------
__global__ void ln_preact_kernel(const float* __restrict__ pre,
                                 const float* __restrict__ g, const float* __restrict__ bb,
                                 float* __restrict__ Z, float* __restrict__ HG,
                                 float* __restrict__ PL)
{
    __shared__ float sh[32];
    long row = blockIdx.x;
    int c = threadIdx.x * 4;
    const float* r = pre + row * (3 * kD);
    float4 v = *reinterpret_cast<const float4*>(r + c);
    float s = v.x + v.y + v.z + v.w;
    float q = v.x * v.x + v.y * v.y + v.z * v.z + v.w * v.w;
    s = blockSum(s, sh);
    q = blockSum(q, sh);
    const float invW = 1.f / (3 * kD);
    float m  = s * invW;
    float rv = rsqrtf(q * invW - m * m + kEPS);
    float n0 = g[c + 0] * ((v.x - m) * rv) + bb[c + 0];
    float n1 = g[c + 1] * ((v.y - m) * rv) + bb[c + 1];
    float n2 = g[c + 2] * ((v.z - m) * rv) + bb[c + 2];
    float n3 = g[c + 3] * ((v.w - m) * rv) + bb[c + 3];
    long rD = row * kD;
    if (c < kD) {
        float4 o = make_float4(sigm(n0), sigm(n1), sigm(n2), sigm(n3));
        *reinterpret_cast<float4*>(Z + rD + c) = o;
    } else if (c < 2 * kD) {
        float4 o = make_float4(sigm(n0), sigm(n1), sigm(n2), sigm(n3));
        *reinterpret_cast<float4*>(HG + rD + (c - kD)) = o;
    } else {
        float4 o = make_float4(n0, n1, n2, n3);
        *reinterpret_cast<float4*>(PL + rD + (c - 2 * kD)) = o;
    }
}

// In-place LN over D=512, output rounded to tf32. block=128, grid=rows.
__global__ void ln512_kernel(float* __restrict__ x,
                             const float* __restrict__ g, const float* __restrict__ b)
{
    __shared__ float sh[32];
    long row = blockIdx.x;
    int c = threadIdx.x * 4;
    float* r = x + row * kD;
    float4 v = *reinterpret_cast<const float4*>(r + c);
    float s = v.x + v.y + v.z + v.w;
    float q = v.x * v.x + v.y * v.y + v.z * v.z + v.w * v.w;
    s = blockSum(s, sh);
    q = blockSum(q, sh);
    const float invW = 1.f / kD;
    float m  = s * invW;
    float rv = rsqrtf(q * invW - m * m + kEPS);
    v.x = tf32r(g[c + 0] * ((v.x - m) * rv) + b[c + 0]);
    v.y = tf32r(g[c + 1] * ((v.y - m) * rv) + b[c + 1]);
    v.z = tf32r(g[c + 2] * ((v.z - m) * rv) + b[c + 2]);
    v.w = tf32r(g[c + 3] * ((v.w - m) * rv) + b[c + 3]);
    *reinterpret_cast<float4*>(r + c) = v;
}

// SRU linear recurrence with batched prefetch: each group of 16 timesteps
// issues all 32 independent loads before the serial FMA chain (MLP 32/thread).
__global__ __launch_bounds__(128)
void scan_kernel(const float* __restrict__ Z, const float* __restrict__ PL,
                 const float* __restrict__ h0, float* __restrict__ ss)
{
    constexpr int BATCH = 16;
    int idx = blockIdx.x * 128 + threadIdx.x;          // b*D + d
    float s = h0[idx];
    const long stride = (long)kB * kD;
    long off = idx;
    for (int g = 0; g < kT / BATCH; g++) {
        float z[BATCH], p[BATCH];
#pragma unroll
        for (int j = 0; j < BATCH; j++) z[j] = __ldg(Z + off + j * stride);
#pragma unroll
        for (int j = 0; j < BATCH; j++) p[j] = __ldg(PL + off + j * stride);
#pragma unroll
        for (int j = 0; j < BATCH; j++) {
            s = (1.f - z[j]) * s + z[j] * p[j];
            ss[off + j * stride] = s;
        }
        off += (long)BATCH * stride;
    }
}

// Masked softmax over S=512; rounded probs into av (GEMM operand),
// exact probs into p_attn output.
__global__ void softmax_kernel(float* __restrict__ av, float* __restrict__ pattn,
                               const int* __restrict__ mlen)
{
    __shared__ float sh[32];
    long row = blockIdx.x;                 // b*T + t
    int b = (int)(row / kT), t = (int)(row % kT);
    int ml = mlen[b];
    float* r = av + row * kS;
    int c = threadIdx.x * 4;
    float4 v = *reinterpret_cast<const float4*>(r + c);
    const float inv = rsqrtf((float)kD);
    float x0 = v.x * inv, x1 = v.y * inv, x2 = v.z * inv, x3 = v.w * inv;
    float mx = -INFINITY;
    if (c + 0 < ml) mx = fmaxf(mx, x0);
    if (c + 1 < ml) mx = fmaxf(mx, x1);
    if (c + 2 < ml) mx = fmaxf(mx, x2);
    if (c + 3 < ml) mx = fmaxf(mx, x3);
    mx = blockMax(mx, sh);
    float e0 = (c + 0 < ml) ? expf(x0 - mx) : 0.f;
    float e1 = (c + 1 < ml) ? expf(x1 - mx) : 0.f;
    float e2 = (c + 2 < ml) ? expf(x2 - mx) : 0.f;
    float e3 = (c + 3 < ml) ? expf(x3 - mx) : 0.f;
    float sum = blockSum(e0 + e1 + e2 + e3, sh);
    float is = 1.f / sum;
    float4 o = make_float4(e0 * is, e1 * is, e2 * is, e3 * is);
    *reinterpret_cast<float4*>(pattn + ((long)t * kB + b) * kS + c) = o;
    float4 oq = make_float4(tf32r(o.x), tf32r(o.y), tf32r(o.z), tf32r(o.w));
    *reinterpret_cast<float4*>(r + c) = oq;
}

// out = (1-hg)*tanh(LN(h1)+LN(h2)) + hg*prev
__global__ void final_kernel(const float* __restrict__ h1, const float* __restrict__ h2,
                             const float* __restrict__ HG, const float* __restrict__ prev,
                             const float* __restrict__ g_h, const float* __restrict__ b_h,
                             const float* __restrict__ g_c, const float* __restrict__ b_c,
                             float* __restrict__ out)
{
    __shared__ float sh[32];
    long row = blockIdx.x;
    int c = threadIdx.x * 4;
    float4 a = *reinterpret_cast<const float4*>(h1 + row * kD + c);
    float4 d = *reinterpret_cast<const float4*>(h2 + row * kD + c);
    float s1 = a.x + a.y + a.z + a.w;
    float q1 = a.x * a.x + a.y * a.y + a.z * a.z + a.w * a.w;
    float s2 = d.x + d.y + d.z + d.w;
    float q2 = d.x * d.x + d.y * d.y + d.z * d.z + d.w * d.w;
    s1 = blockSum(s1, sh);
    q1 = blockSum(q1, sh);
    s2 = blockSum(s2, sh);
    q2 = blockSum(q2, sh);
    const float invW = 1.f / kD;
    float m1 = s1 * invW, r1 = rsqrtf(q1 * invW - m1 * m1 + kEPS);
    float m2 = s2 * invW, r2 = rsqrtf(q2 * invW - m2 * m2 + kEPS);
    float4 hg = *reinterpret_cast<const float4*>(HG + row * kD + c);
    float4 pv = *reinterpret_cast<const float4*>(prev + row * kD + c);
    float t0 = tanhf(g_h[c + 0] * ((a.x - m1) * r1) + b_h[c + 0] +
                     g_c[c + 0] * ((d.x - m2) * r2) + b_c[c + 0]);
    float t1 = tanhf(g_h[c + 1] * ((a.y - m1) * r1) + b_h[c + 1] +
                     g_c[c + 1] * ((d.y - m2) * r2) + b_c[c + 1]);
    float t2 = tanhf(g_h[c + 2] * ((a.z - m1) * r1) + b_h[c + 2] +
                     g_c[c + 2] * ((d.z - m2) * r2) + b_c[c + 2]);
    float t3 = tanhf(g_h[c + 3] * ((a.w - m1) * r1) + b_h[c + 3] +
                     g_c[c + 3] * ((d.w - m2) * r2) + b_c[c + 3]);
    float4 o;
    o.x = (1.f - hg.x) * t0 + hg.x * pv.x;
    o.y = (1.f - hg.y) * t1 + hg.y * pv.y;
    o.z = (1.f - hg.z) * t2 + hg.z * pv.z;
    o.w = (1.f - hg.w) * t3 + hg.w * pv.w;
    *reinterpret_cast<float4*>(out + row * kD + c) = o;
}

// ---------------------------------------------------------------------------
// Launch
// ---------------------------------------------------------------------------
extern "C" void kernel_launch(void* const* d_in, const int* in_sizes, int n_in,
                              void* d_out, int out_size)
{
    int i_prev = -1, i_enc = -1, i_hidden = -1, i_ml = -1, i_Win = -1;
    int w4[4] = {-1, -1, -1, -1}; int n4 = 0;
    int p2[2] = {-1, -1};         int np = 0;
    int v8[8] = {-1, -1, -1, -1, -1, -1, -1, -1}; int nv = 0;
    for (int i = 0; i < n_in; i++) {
        switch (in_sizes[i]) {
            case 8388608: if (i_prev < 0) i_prev = i; else i_enc = i; break;
            case 16384:   i_hidden = i; break;
            case 32:      i_ml = i; break;
            case 786432:  i_Win = i; break;
            case 262144:  if (n4 < 4) w4[n4++] = i; break;
            case 1536:    if (np < 2) p2[np++] = i; break;
            case 512:     if (nv < 8) v8[nv++] = i; break;
            default: break;
        }
    }
    const float* prev   = (const float*)d_in[i_prev];
    const float* hidden = (const float*)d_in[i_hidden];
    const float* enc    = (const float*)d_in[i_enc];
    const int*   mlen   = (const int*)d_in[i_ml];
    const float* W_in   = (const float*)d_in[i_Win];
    const float* W_enc  = (const float*)d_in[w4[0]];
    const float* W_att  = (const float*)d_in[w4[1]];
    const float* W_hid  = (const float*)d_in[w4[2]];
    const float* W_ctx  = (const float*)d_in[w4[3]];
    const float* g_pre  = (const float*)d_in[p2[0]];
    const float* b_pre  = (const float*)d_in[p2[1]];
    const float* g_enc  = (const float*)d_in[v8[0]];
    const float* b_enc  = (const float*)d_in[v8[1]];
    const float* g_att  = (const float*)d_in[v8[2]];
    const float* b_att  = (const float*)d_in[v8[3]];
    const float* g_h    = (const float*)d_in[v8[4]];
    const float* b_h    = (const float*)d_in[v8[5]];
    const float* g_c    = (const float*)d_in[v8[6]];
    const float* b_c    = (const float*)d_in[v8[7]];

    float* sc = nullptr;
    cudaGetSymbolAddress((void**)&sc, g_scratch);

    float* out       = (float*)d_out;            // [T,B,D]
    float* out_hid   = out + kTBD;               // [B,D]
    float* out_pattn = out_hid + (long)kB * kD;  // [T,B,S]

    cudaFuncSetAttribute(gemm_mma_kernel,
                         cudaFuncAttributeMaxDynamicSharedMemorySize, GEMM_SMEM);

    dim3 tb(32, 8);
    const float invsq = rsqrtf((float)kD);

    // side stream + fork/join events (capture-safe; not destroyed mid-capture)
    cudaStream_t s1;
    cudaStreamCreateWithFlags(&s1, cudaStreamNonBlocking);
    cudaEvent_t eW, eP, eS, eH;
    cudaEventCreateWithFlags(&eW, cudaEventDisableTiming);
    cudaEventCreateWithFlags(&eP, cudaEventDisableTiming);
    cudaEventCreateWithFlags(&eS, cudaEventDisableTiming);
    cudaEventCreateWithFlags(&eH, cudaEventDisableTiming);

    // 0) weight transposes on stream 0 (-> K-major [N,K], rounded tf32)
    transpose_kernel<<<dim3(16, 16, 3), tb>>>(W_in, sc + OF_WTIN, kD, 3 * kD,
                                              512, (long)kD * kD);
    transpose4_kernel<<<dim3(16, 16, 4), tb>>>(W_enc, W_att, W_hid, W_ctx,
                                               sc + OF_WTENC, sc + OF_WTATT,
                                               sc + OF_WTHID, sc + OF_WTCTX);
    cudaEventRecord(eW, 0);

    // -- side stream: enc chain (pctx) --
    cudaStreamWaitEvent(s1, eW, 0);
    gemm_mma_kernel<<<dim3(4, 128, 1), 256, GEMM_SMEM, s1>>>(
        enc, sc + OF_WTENC, sc + OF_PCTX, 512, 512, 512, 512, 0, 0, 0, 1.f);
    ln512_kernel<<<(unsigned)kTB, 128, 0, s1>>>(sc + OF_PCTX, g_enc, b_enc);
    transpose_kernel<<<dim3(16, 16, 32), tb, 0, s1>>>(sc + OF_PCTX, sc + OF_PCTXT,
                                                      kS, kD, (long)kS * kD,
                                                      (long)kD * kS);
    cudaEventRecord(eP, s1);

    // -- main stream: preact chain --
    gemm_mma_kernel<<<dim3(12, 128, 1), 256, GEMM_SMEM>>>(
        prev, sc + OF_WTIN, sc + OF_PRE, 512, 512, 512, 1536, 0, 0, 0, 1.f);
    ln_preact_kernel<<<(unsigned)kTB, 384>>>(sc + OF_PRE, g_pre, b_pre,
                                             sc + OF_Z, sc + OF_HG, sc + OF_PL);
    scan_kernel<<<(kB * kD) / 128, 128>>>(sc + OF_Z, sc + OF_PL, hidden, sc + OF_SS);
    cudaEventRecord(eS, 0);
    gemm_mma_kernel<<<dim3(4, 128, 1), 256, GEMM_SMEM>>>(
        sc + OF_SS, sc + OF_WTATT, sc + OF_ATT, 512, 512, 512, 512, 0, 0, 0, 1.f);
    ln512_kernel<<<(unsigned)kTB, 128>>>(sc + OF_ATT, g_att, b_att);

    // -- side stream: h1 = ss @ W_hidden (after scan) --
    cudaStreamWaitEvent(s1, eS, 0);
    gemm_mma_kernel<<<dim3(4, 128, 1), 256, GEMM_SMEM, s1>>>(
        sc + OF_SS, sc + OF_WTHID, sc + OF_H1, 512, 512, 512, 512, 0, 0, 0, 1.f);
    cudaEventRecord(eH, s1);

    // -- main stream: attention (needs pctx) --
    cudaStreamWaitEvent(0, eP, 0);
    gemm_mma_kernel<<<dim3(4, 4, 32), 256, GEMM_SMEM>>>(
        sc + OF_ATT, sc + OF_PCTX, sc + OF_AV, 512,
        (long)kB * kD, 512, 512, kD, (long)kS * kD, (long)kT * kS, 1.f);
    softmax_kernel<<<(unsigned)(kB * kT), 128>>>(sc + OF_AV, out_pattn, mlen);
    gemm_mma_kernel<<<dim3(4, 4, 32), 256, GEMM_SMEM>>>(
        sc + OF_AV, sc + OF_PCTXT, sc + OF_AO, 512,
        512, 512, (long)kB * kD, (long)kT * kS, (long)kD * kS, kD, invsq);
    gemm_mma_kernel<<<dim3(4, 128, 1), 256, GEMM_SMEM>>>(
        sc + OF_AO, sc + OF_WTCTX, sc + OF_H2, 512, 512, 512, 512, 0, 0, 0, 1.f);

    // join h1, final blend
    cudaStreamWaitEvent(0, eH, 0);
    final_kernel<<<(unsigned)kTB, 128>>>(sc + OF_H1, sc + OF_H2, sc + OF_HG, prev,
                                         g_h, b_h, g_c, b_c, out);
    cudaMemcpyAsync(out_hid, sc + OF_SS + (long)(kT - 1) * kB * kD,
                    (size_t)kB * kD * sizeof(float), cudaMemcpyDeviceToDevice, 0);
    // (stream/events intentionally leaked: destroying a fork stream mid-capture
    //  invalidates the capture; a handful of host objects across <=5 calls is fine)
}